// round 11
// baseline (speedup 1.0000x reference)
#include <cuda_runtime.h>
#include <math.h>

#define BB   128
#define HH   512
#define INP  256
#define EE   256
#define VV   20000
#define TSRC 64
#define TTRG 50

// logits GEMM tiling: BM=128, BN=48, BK=32, 192 threads, 3 CTAs/SM
#define BN_L 48
#define BK_L 32
#define NT_L 417          // ceil(20000/48)
#define SA_STRIDE 132     // padded [BK][128]
#define SB_STRIDE 52      // padded [BK][48]

// ---------------- persistent device scratch (no allocations) ----------------
__device__ float g_hA[BB*HH];
__device__ float g_hB[BB*HH];
__device__ float g_pmax[BB*NT_L];
__device__ float g_psum[BB*NT_L];
__device__ int   g_eid[BB];                // decoder carry: token id
__device__ float g_rate[BB];               // decoder carry: rate
__device__ float g_ph[BB*HH];              // relu(pr1)

__device__ __forceinline__ float sigf(float x){ return 1.f/(1.f+expf(-x)); }
__device__ __forceinline__ float dot4(float4 a, float4 b){
  return a.x*b.x + a.y*b.y + a.z*b.z + a.w*b.w;
}
// merge (max-value, sum-of-exp-relative-to-max). Safe with -FLT_MAX sentinel.
__device__ __forceinline__ void merge2(float& m, float& s, float om, float os){
  if (om > m){ s = s*__expf(m-om) + os; m = om; }
  else       { s = s + os*__expf(om-m); }
}

// ---------------- init: zero step-0 outputs, h0, seed decoder carry ----------
__global__ void k_init(const int* __restrict__ trg_eid,
                       const float* __restrict__ trg_rate,
                       float* __restrict__ out)
{
  long idx = (long)blockIdx.x*blockDim.x + threadIdx.x;
  const long NZ = (long)BB*VV/4;               // 640000 float4
  float4 z = make_float4(0.f,0.f,0.f,0.f);
  if (idx < NZ) ((float4*)out)[idx] = z;       // eid_result[0] = 0
  if (idx < BB*HH/4) ((float4*)g_hA)[idx] = z; // h0 = 0
  if (idx < BB) {
    out[(long)TTRG*BB*VV + idx] = 0.f;         // rate_result[0] = 0
    g_eid[idx]  = trg_eid[idx];                // trg_eid[0, b]
    g_rate[idx] = trg_rate[idx];               // trg_rate[0, b]
  }
}

// ---------------- encoder GRU step (j-block 2, k-split x4, 512 thr) ----------
// grid 256 (2 hidden units each), block 512: tid = b + 128*kq.
// Same K-partition and reduction order as the passing R10 kernel.
__global__ __launch_bounds__(512) void k_enc(
  const float* __restrict__ src, const int* __restrict__ src_len,
  const float* __restrict__ Wi, const float* __restrict__ Wh,
  const float* __restrict__ bi, const float* __restrict__ bh, int t)
{
  __shared__ float sbuf[6*INP + 6*HH];     // 18KB; overlay sP[8*512] later
  float* sWi = sbuf;                        // 6 rows x INP  (r = gate*2 + jj)
  float* sWh = sbuf + 6*INP;                // 6 rows x HH
  const float* hin  = (t & 1) ? g_hB : g_hA;
  float*       hout = (t & 1) ? g_hA : g_hB;
  int j0 = blockIdx.x * 2;
  int tid = threadIdx.x;
  int b = tid & 127, kq = tid >> 7;
  for (int p = tid; p < 6*(INP/4); p += 512){
    int r = p >> 6, c4 = p & 63;
    int g = r >> 1, jj = r & 1;
    ((float4*)sWi)[p] = ((const float4*)(Wi + (g*HH + j0 + jj)*INP))[c4];
  }
  for (int p = tid; p < 6*(HH/4); p += 512){
    int r = p >> 7, c4 = p & 127;
    int g = r >> 1, jj = r & 1;
    ((float4*)sWh)[p] = ((const float4*)(Wh + (g*HH + j0 + jj)*HH))[c4];
  }
  __syncthreads();
  const float* x = src + ((long)t*BB + b)*INP;
  const float* h = hin + b*HH;
  float aR[2]={0,0}, aZ[2]={0,0}, aNX[2]={0,0}, aNH[2]={0,0};
  {
    int k0 = kq*64;
    #pragma unroll 4
    for (int k = k0; k < k0+64; k += 4){
      float4 xv = *(const float4*)(x + k);
      #pragma unroll
      for (int jj = 0; jj < 2; jj++){
        aR[jj]  += dot4(xv, *(const float4*)&sWi[(    jj)*INP + k]);
        aZ[jj]  += dot4(xv, *(const float4*)&sWi[(2 + jj)*INP + k]);
        aNX[jj] += dot4(xv, *(const float4*)&sWi[(4 + jj)*INP + k]);
      }
    }
  }
  {
    int k0 = kq*128;
    #pragma unroll 4
    for (int k = k0; k < k0+128; k += 4){
      float4 hv = *(const float4*)(h + k);
      #pragma unroll
      for (int jj = 0; jj < 2; jj++){
        aR[jj]  += dot4(hv, *(const float4*)&sWh[(    jj)*HH + k]);
        aZ[jj]  += dot4(hv, *(const float4*)&sWh[(2 + jj)*HH + k]);
        aNH[jj] += dot4(hv, *(const float4*)&sWh[(4 + jj)*HH + k]);
      }
    }
  }
  __syncthreads();                          // weight reads done
  float* sP = sbuf;                         // overlay: 8 x 512 partials
  #pragma unroll
  for (int jj = 0; jj < 2; jj++){
    sP[(0 + jj)*512 + tid] = aR[jj];
    sP[(2 + jj)*512 + tid] = aZ[jj];
    sP[(4 + jj)*512 + tid] = aNX[jj];
    sP[(6 + jj)*512 + tid] = aNH[jj];
  }
  __syncthreads();
  if (tid < 128){
    int bb = tid;
    bool act = t < src_len[bb];
    const float* hb = hin + bb*HH;
    #pragma unroll
    for (int jj = 0; jj < 2; jj++){
      float vR  = ((sP[(0+jj)*512+bb] + sP[(0+jj)*512+bb+128])
                 + (sP[(0+jj)*512+bb+256] + sP[(0+jj)*512+bb+384]));
      float vZ  = ((sP[(2+jj)*512+bb] + sP[(2+jj)*512+bb+128])
                 + (sP[(2+jj)*512+bb+256] + sP[(2+jj)*512+bb+384]));
      float vNX = ((sP[(4+jj)*512+bb] + sP[(4+jj)*512+bb+128])
                 + (sP[(4+jj)*512+bb+256] + sP[(4+jj)*512+bb+384]));
      float vNH = ((sP[(6+jj)*512+bb] + sP[(6+jj)*512+bb+128])
                 + (sP[(6+jj)*512+bb+256] + sP[(6+jj)*512+bb+384]));
      int j = j0 + jj;
      float r = sigf(vR + bi[j]      + bh[j]);
      float z = sigf(vZ + bi[HH+j]   + bh[HH+j]);
      float n = tanhf(vNX + bi[2*HH+j] + r*(vNH + bh[2*HH+j]));
      float hv = (1.f - z)*n + z*hb[j];
      hout[bb*HH + j] = act ? hv : hb[j];
    }
  }
}

// ---------------- decoder GRU step (j-block 2, k-split x4, 512 thr) ----------
__global__ __launch_bounds__(512) void k_dec_gru(
  const float* __restrict__ emb,
  const float* __restrict__ Wi, const float* __restrict__ Wh,
  const float* __restrict__ bi, const float* __restrict__ bh, int i)
{
  __shared__ float sbuf[6*260 + 6*HH];     // 18.1KB; overlay sP[8*512]
  float* sWi = sbuf;                        // 6 rows x 260 (257 padded)
  float* sWh = sbuf + 6*260;
  const float* hin  = (i & 1) ? g_hB : g_hA;
  float*       hout = (i & 1) ? g_hA : g_hB;
  int j0 = blockIdx.x * 2;
  int tid = threadIdx.x;
  int b = tid & 127, kq = tid >> 7;
  for (int p = tid; p < 6*257; p += 512){
    int r = p / 257, c = p - r*257;
    int g = r >> 1, jj = r & 1;
    sWi[r*260 + c] = Wi[(g*HH + j0 + jj)*257 + c];
  }
  for (int p = tid; p < 6*(HH/4); p += 512){
    int r = p >> 7, c4 = p & 127;
    int g = r >> 1, jj = r & 1;
    ((float4*)sWh)[p] = ((const float4*)(Wh + (g*HH + j0 + jj)*HH))[c4];
  }
  __syncthreads();
  const float* xe = emb + (long)g_eid[b]*EE;
  const float* h = hin + b*HH;
  float aR[2]={0,0}, aZ[2]={0,0}, aNX[2]={0,0}, aNH[2]={0,0};
  {
    int k0 = kq*64;
    #pragma unroll 4
    for (int k = k0; k < k0+64; k += 4){
      float4 xv = *(const float4*)(xe + k);
      #pragma unroll
      for (int jj = 0; jj < 2; jj++){
        aR[jj]  += dot4(xv, *(const float4*)&sWi[(    jj)*260 + k]);
        aZ[jj]  += dot4(xv, *(const float4*)&sWi[(2 + jj)*260 + k]);
        aNX[jj] += dot4(xv, *(const float4*)&sWi[(4 + jj)*260 + k]);
      }
    }
  }
  if (kq == 0){                             // rate column (k = 256)
    float rate = g_rate[b];
    #pragma unroll
    for (int jj = 0; jj < 2; jj++){
      aR[jj]  += rate * sWi[(    jj)*260 + 256];
      aZ[jj]  += rate * sWi[(2 + jj)*260 + 256];
      aNX[jj] += rate * sWi[(4 + jj)*260 + 256];
    }
  }
  {
    int k0 = kq*128;
    #pragma unroll 4
    for (int k = k0; k < k0+128; k += 4){
      float4 hv = *(const float4*)(h + k);
      #pragma unroll
      for (int jj = 0; jj < 2; jj++){
        aR[jj]  += dot4(hv, *(const float4*)&sWh[(    jj)*HH + k]);
        aZ[jj]  += dot4(hv, *(const float4*)&sWh[(2 + jj)*HH + k]);
        aNH[jj] += dot4(hv, *(const float4*)&sWh[(4 + jj)*HH + k]);
      }
    }
  }
  __syncthreads();
  float* sP = sbuf;
  #pragma unroll
  for (int jj = 0; jj < 2; jj++){
    sP[(0 + jj)*512 + tid] = aR[jj];
    sP[(2 + jj)*512 + tid] = aZ[jj];
    sP[(4 + jj)*512 + tid] = aNX[jj];
    sP[(6 + jj)*512 + tid] = aNH[jj];
  }
  __syncthreads();
  if (tid < 128){
    int bb = tid;
    const float* hb = hin + bb*HH;
    #pragma unroll
    for (int jj = 0; jj < 2; jj++){
      float vR  = ((sP[(0+jj)*512+bb] + sP[(0+jj)*512+bb+128])
                 + (sP[(0+jj)*512+bb+256] + sP[(0+jj)*512+bb+384]));
      float vZ  = ((sP[(2+jj)*512+bb] + sP[(2+jj)*512+bb+128])
                 + (sP[(2+jj)*512+bb+256] + sP[(2+jj)*512+bb+384]));
      float vNX = ((sP[(4+jj)*512+bb] + sP[(4+jj)*512+bb+128])
                 + (sP[(4+jj)*512+bb+256] + sP[(4+jj)*512+bb+384]));
      float vNH = ((sP[(6+jj)*512+bb] + sP[(6+jj)*512+bb+128])
                 + (sP[(6+jj)*512+bb+256] + sP[(6+jj)*512+bb+384]));
      int j = j0 + jj;
      float r = sigf(vR + bi[j]      + bh[j]);
      float z = sigf(vZ + bi[HH+j]   + bh[HH+j]);
      float n = tanhf(vNX + bi[2*HH+j] + r*(vNH + bh[2*HH+j]));
      hout[bb*HH + j] = (1.f - z)*n + z*hb[j];
    }
  }
}

// ---------------- logits GEMM: out[s] = h @ We^T + be (raw logits) -----------
// BM=128, BN=48, BK=32, 192 threads (ty=16 x 8 rows, tx=12 x 4 cols), occ 3.
// 417 tiles => max 3 tiles/SM (9.44M MAC) vs 313x64's 3x4.19M = 12.6M.
// Writes raw logits straight into the output slice; stats via smem overlay.
__global__ __launch_bounds__(192, 3) void k_logits(
  const float* __restrict__ We, const float* __restrict__ be,
  float* __restrict__ out, int i, int s)
{
  __shared__ float sA[BK_L*SA_STRIDE];     // 16.9KB
  __shared__ float sB[BK_L*SB_STRIDE];     // 6.7KB
  const float* h = (i & 1) ? g_hA : g_hB;
  int tile = blockIdx.x;
  int n0 = tile * BN_L;
  int t = threadIdx.x;
  int tx = t % 12, ty = t / 12;            // ty in 0..15
  float acc[8][4];
  #pragma unroll
  for (int a = 0; a < 8; a++)
    #pragma unroll
    for (int c = 0; c < 4; c++) acc[a][c] = 0.f;

  for (int k0 = 0; k0 < HH; k0 += BK_L){
    for (int p = t; p < 1024; p += 192){          // A tile: 128x32 (transpose)
      int row = p >> 3, c4 = p & 7;
      float4 v = *(const float4*)(h + row*HH + k0 + c4*4);
      sA[(c4*4+0)*SA_STRIDE + row] = v.x;
      sA[(c4*4+1)*SA_STRIDE + row] = v.y;
      sA[(c4*4+2)*SA_STRIDE + row] = v.z;
      sA[(c4*4+3)*SA_STRIDE + row] = v.w;
    }
    for (int p = t; p < 384; p += 192){           // B tile: 48x32 (transpose)
      int row = p >> 3, c4 = p & 7;
      int n = n0 + row; if (n >= VV) n = 0;       // clamp (discarded later)
      float4 v = *(const float4*)(We + (long)n*HH + k0 + c4*4);
      sB[(c4*4+0)*SB_STRIDE + row] = v.x;
      sB[(c4*4+1)*SB_STRIDE + row] = v.y;
      sB[(c4*4+2)*SB_STRIDE + row] = v.z;
      sB[(c4*4+3)*SB_STRIDE + row] = v.w;
    }
    __syncthreads();
    float loc[8][4];
    #pragma unroll
    for (int a = 0; a < 8; a++)
      #pragma unroll
      for (int c = 0; c < 4; c++) loc[a][c] = 0.f;
    #pragma unroll
    for (int kk = 0; kk < BK_L; kk++){
      float4 a01 = *(const float4*)&sA[kk*SA_STRIDE + ty*8];
      float4 a23 = *(const float4*)&sA[kk*SA_STRIDE + ty*8 + 4];
      float4 bv  = *(const float4*)&sB[kk*SB_STRIDE + tx*4];
      float a[8] = {a01.x,a01.y,a01.z,a01.w,a23.x,a23.y,a23.z,a23.w};
      float bf[4] = {bv.x,bv.y,bv.z,bv.w};
      #pragma unroll
      for (int ii = 0; ii < 8; ii++)
        #pragma unroll
        for (int jj = 0; jj < 4; jj++) loc[ii][jj] += a[ii]*bf[jj];
    }
    #pragma unroll
    for (int ii = 0; ii < 8; ii++)
      #pragma unroll
      for (int jj = 0; jj < 4; jj++)
        acc[ii][jj] = __fadd_rn(acc[ii][jj], loc[ii][jj]);
    __syncthreads();
  }

  // epilogue: bias, store raw logits to out, per-(tile,row) max/sumexp
  float bias[4];
  #pragma unroll
  for (int jj = 0; jj < 4; jj++){
    int n = n0 + tx*4 + jj;
    bias[jj] = (n < VV) ? be[n] : 0.f;
  }
  int nbase = n0 + tx*4;
  bool fullvec = (nbase + 3 < VV);
  float* sM = sA;                   // overlay: 12 x 128 max
  float* sS = sA + 12*128;          // overlay: 12 x 128 sumexp (fits 16.9KB)
  float* orow = out + (long)s*BB*VV;
  #pragma unroll
  for (int ii = 0; ii < 8; ii++){
    int r = ty*8 + ii;
    float vals[4];
    float m = -3.402823466e38f;
    bool anyv = false;
    #pragma unroll
    for (int jj = 0; jj < 4; jj++){
      int n = nbase + jj;
      float v = acc[ii][jj] + bias[jj];
      vals[jj] = v;
      if (n < VV){ anyv = true; if (v > m) m = v; }
    }
    float ss = 0.f;
    if (anyv){
      #pragma unroll
      for (int jj = 0; jj < 4; jj++){
        int n = nbase + jj;
        if (n < VV) ss += __expf(vals[jj] - m);
      }
    }
    if (fullvec){
      *(float4*)&orow[(long)r*VV + nbase] = make_float4(vals[0],vals[1],vals[2],vals[3]);
    } else {
      #pragma unroll
      for (int jj = 0; jj < 4; jj++){
        int n = nbase + jj;
        if (n < VV) orow[(long)r*VV + n] = vals[jj];
      }
    }
    sM[tx*128 + r] = m;
    sS[tx*128 + r] = ss;
  }
  __syncthreads();
  if (t < 128){
    int r = t;
    float m = -3.402823466e38f, ss = 0.f;
    #pragma unroll
    for (int q = 0; q < 12; q++)
      merge2(m, ss, sM[q*128 + r], sS[q*128 + r]);
    g_pmax[r*NT_L + tile] = m;
    g_psum[r*NT_L + tile] = ss;
  }
}

// ---------------- fused: row reduce + in-place logp + argmax -----------------
// Per block = one batch row. Reduces 417 tile partials to (m, ls), then
// rewrites out[s,b,:] in place: logp = fl(fl(x - m) - ls), and argmaxes the
// ROUNDED values, first-index ties (matches jnp.argmax(log_softmax(x))).
__global__ __launch_bounds__(512) void k_write(float* __restrict__ out, int s)
{
  int b = blockIdx.x, t = threadIdx.x;
  __shared__ float sm[512]; __shared__ float ssm[512];
  float m = -3.402823466e38f; float ssum = 0.f;
  for (int tile = t; tile < NT_L; tile += 512)
    merge2(m, ssum, g_pmax[b*NT_L+tile], g_psum[b*NT_L+tile]);
  sm[t] = m; ssm[t] = ssum;
  __syncthreads();
  for (int off = 256; off; off >>= 1){
    if (t < off){
      float m2 = sm[t]; float s2 = ssm[t];
      merge2(m2, s2, sm[t+off], ssm[t+off]);
      sm[t] = m2; ssm[t] = s2;
    }
    __syncthreads();
  }
  m = sm[0];
  float ls = logf(ssm[0]);
  __syncthreads();

  float4* rowp = (float4*)(out + (long)s*BB*VV + (long)b*VV);
  float bm = -3.402823466e38f; int bi_ = 0x7fffffff;
  for (int p = t; p < VV/4; p += 512){
    float4 v = rowp[p];
    float r0 = __fsub_rn(__fsub_rn(v.x, m), ls);
    float r1 = __fsub_rn(__fsub_rn(v.y, m), ls);
    float r2 = __fsub_rn(__fsub_rn(v.z, m), ls);
    float r3 = __fsub_rn(__fsub_rn(v.w, m), ls);
    rowp[p] = make_float4(r0, r1, r2, r3);
    int n = p*4;   // ascending + strictly-greater => thread-local first idx
    if (r0 > bm){ bm = r0; bi_ = n;     }
    if (r1 > bm){ bm = r1; bi_ = n + 1; }
    if (r2 > bm){ bm = r2; bi_ = n + 2; }
    if (r3 > bm){ bm = r3; bi_ = n + 3; }
  }
  __shared__ float sv[512]; __shared__ int si[512];
  sv[t] = bm; si[t] = bi_;
  __syncthreads();
  for (int off = 256; off; off >>= 1){
    if (t < off){
      float ov = sv[t+off]; int oi = si[t+off];
      if (ov > sv[t] || (ov == sv[t] && oi < si[t])){ sv[t] = ov; si[t] = oi; }
    }
    __syncthreads();
  }
  if (t == 0) g_eid[b] = si[0];
}

// ---------------- pr1 = relu([emb[eid], h] @ W1^T + b1) ----------------------
__global__ __launch_bounds__(128) void k_pr1(
  const float* __restrict__ emb, const float* __restrict__ W1,
  const float* __restrict__ b1, int i)
{
  __shared__ float sW[4*768];
  const float* h = (i & 1) ? g_hA : g_hB;
  int j0 = blockIdx.x*4, tid = threadIdx.x;
  for (int p = tid; p < 4*192; p += 128){
    int r = p / 192, c4 = p - r*192;
    ((float4*)&sW[r*768])[c4] = ((const float4*)(W1 + (j0+r)*768))[c4];
  }
  __syncthreads();
  int b = tid;
  const float* xe = emb + (long)g_eid[b]*EE;   // g_eid already = next_eid
  const float* hb = h + b*HH;
  float acc[4] = {0,0,0,0};
  #pragma unroll 4
  for (int k = 0; k < EE; k += 4){
    float4 xv = *(const float4*)(xe + k);
    #pragma unroll
    for (int jj = 0; jj < 4; jj++)
      acc[jj] += dot4(xv, *(const float4*)&sW[jj*768 + k]);
  }
  #pragma unroll 4
  for (int k = 0; k < HH; k += 4){
    float4 hv = *(const float4*)(hb + k);
    #pragma unroll
    for (int jj = 0; jj < 4; jj++)
      acc[jj] += dot4(hv, *(const float4*)&sW[jj*768 + 256 + k]);
  }
  #pragma unroll
  for (int jj = 0; jj < 4; jj++)
    g_ph[b*HH + j0 + jj] = fmaxf(acc[jj] + b1[j0+jj], 0.f);
}

// ---------------- pr = sigmoid(relu(pr1) @ W2^T + b2) ------------------------
__global__ __launch_bounds__(128) void k_pr2(
  const float* __restrict__ W2, const float* __restrict__ b2,
  float* __restrict__ out, int s)
{
  int b = blockIdx.x, t = threadIdx.x;
  float acc = 0.f;
  for (int k = t; k < HH; k += 128) acc += g_ph[b*HH + k] * W2[k];
  __shared__ float red[128];
  red[t] = acc;
  __syncthreads();
  for (int off = 64; off; off >>= 1){
    if (t < off) red[t] = __fadd_rn(red[t], red[t+off]);
    __syncthreads();
  }
  if (t == 0){
    float pr = sigf(red[0] + b2[0]);
    out[(long)TTRG*BB*VV + (long)s*BB + b] = pr;
    g_rate[b] = pr;
  }
}

// ---------------- host driver ------------------------------------------------
extern "C" void kernel_launch(void* const* d_in, const int* in_sizes, int n_in,
                              void* d_out, int out_size)
{
  (void)in_sizes; (void)n_in; (void)out_size;
  const float* src      = (const float*)d_in[0];
  const int*   src_len  = (const int*)  d_in[1];
  const int*   trg_eid  = (const int*)  d_in[2];
  const float* trg_rate = (const float*)d_in[3];
  const float* emb      = (const float*)d_in[4];
  const float* enc_Wi   = (const float*)d_in[5];
  const float* enc_Wh   = (const float*)d_in[6];
  const float* enc_bi   = (const float*)d_in[7];
  const float* enc_bh   = (const float*)d_in[8];
  const float* dec_Wi   = (const float*)d_in[9];
  const float* dec_Wh   = (const float*)d_in[10];
  const float* dec_bi   = (const float*)d_in[11];
  const float* dec_bh   = (const float*)d_in[12];
  const float* We       = (const float*)d_in[13];
  const float* be       = (const float*)d_in[14];
  const float* W1       = (const float*)d_in[15];
  const float* b1       = (const float*)d_in[16];
  const float* W2       = (const float*)d_in[17];
  const float* b2       = (const float*)d_in[18];
  float* out = (float*)d_out;

  k_init<<<2560, 256>>>(trg_eid, trg_rate, out);

  // ---- encoder: 64 sequential GRU steps (h ping-pongs A<->B, ends in A)
  for (int t = 0; t < TSRC; t++)
    k_enc<<<256, 512>>>(src, src_len, enc_Wi, enc_Wh, enc_bi, enc_bh, t);

  // ---- decoder: 49 sequential steps, output index s = i+1
  for (int i = 0; i < TTRG - 1; i++){
    k_dec_gru<<<256, 512>>>(emb, dec_Wi, dec_Wh, dec_bi, dec_bh, i);
    k_logits<<<NT_L, 192>>>(We, be, out, i, i + 1);   // raw logits -> out[s]
    k_write<<<128, 512>>>(out, i + 1);                // reduce + logp + argmax
    k_pr1<<<128, 128>>>(emb, W1, b1, i);
    k_pr2<<<128, 128>>>(W2, b2, out, i + 1);
  }
}

// round 12
// speedup vs baseline: 1.0072x; 1.0072x over previous
#include <cuda_runtime.h>
#include <math.h>

#define BB   128
#define HH   512
#define INP  256
#define EE   256
#define VV   20000
#define TSRC 64
#define TTRG 50

// logits GEMM tiling: BM=128, BN=48, BK=32, 192 threads, 3 CTAs/SM
#define BN_L 48
#define BK_L 32
#define NT_L 417          // ceil(20000/48)
#define SA_STRIDE 132     // padded [BK][128]
#define SB_STRIDE 52      // padded [BK][48]

// ---------------- persistent device scratch (no allocations) ----------------
__device__ float g_hA[BB*HH];
__device__ float g_hB[BB*HH];
__device__ float g_pmax[BB*NT_L];
__device__ float g_psum[BB*NT_L];
__device__ int   g_eid[BB];                // decoder carry: token id
__device__ float g_rate[BB];               // decoder carry: rate

__device__ __forceinline__ float sigf(float x){ return 1.f/(1.f+expf(-x)); }
__device__ __forceinline__ float dot4(float4 a, float4 b){
  return a.x*b.x + a.y*b.y + a.z*b.z + a.w*b.w;
}
// merge (max-value, sum-of-exp-relative-to-max). Safe with -FLT_MAX sentinel.
__device__ __forceinline__ void merge2(float& m, float& s, float om, float os){
  if (om > m){ s = s*__expf(m-om) + os; m = om; }
  else       { s = s + os*__expf(om-m); }
}

// ---------------- init: zero step-0 outputs, h0, seed decoder carry ----------
__global__ void k_init(const int* __restrict__ trg_eid,
                       const float* __restrict__ trg_rate,
                       float* __restrict__ out)
{
  long idx = (long)blockIdx.x*blockDim.x + threadIdx.x;
  const long NZ = (long)BB*VV/4;               // 640000 float4
  float4 z = make_float4(0.f,0.f,0.f,0.f);
  if (idx < NZ) ((float4*)out)[idx] = z;       // eid_result[0] = 0
  if (idx < BB*HH/4) ((float4*)g_hA)[idx] = z; // h0 = 0
  if (idx < BB) {
    out[(long)TTRG*BB*VV + idx] = 0.f;         // rate_result[0] = 0
    g_eid[idx]  = trg_eid[idx];                // trg_eid[0, b]
    g_rate[idx] = trg_rate[idx];               // trg_rate[0, b]
  }
}

// ---------------- encoder GRU step (k-split x4, 512 threads) -----------------
// R10 version (measured 30.2us): grid 128 (4 hidden units each), block 512:
// tid = b + 128*kq. Partials reduced through smem overlaid on weight buffer.
__global__ __launch_bounds__(512) void k_enc(
  const float* __restrict__ src, const int* __restrict__ src_len,
  const float* __restrict__ Wi, const float* __restrict__ Wh,
  const float* __restrict__ bi, const float* __restrict__ bh, int t)
{
  __shared__ float sbuf[12*INP + 12*HH];   // 36KB; later overlaid by sP[16*512]
  float* sWi = sbuf;                        // 12 rows x INP
  float* sWh = sbuf + 12*INP;               // 12 rows x HH
  const float* hin  = (t & 1) ? g_hB : g_hA;
  float*       hout = (t & 1) ? g_hA : g_hB;
  int j0 = blockIdx.x * 4;
  int tid = threadIdx.x;
  int b = tid & 127, kq = tid >> 7;
  for (int p = tid; p < 12*(INP/4); p += 512){
    int r = p >> 6, c4 = p & 63;
    int g = r >> 2, jj = r & 3;
    ((float4*)sWi)[p] = ((const float4*)(Wi + (g*HH + j0 + jj)*INP))[c4];
  }
  for (int p = tid; p < 12*(HH/4); p += 512){
    int r = p >> 7, c4 = p & 127;
    int g = r >> 2, jj = r & 3;
    ((float4*)sWh)[p] = ((const float4*)(Wh + (g*HH + j0 + jj)*HH))[c4];
  }
  __syncthreads();
  const float* x = src + ((long)t*BB + b)*INP;
  const float* h = hin + b*HH;
  float aR[4]={0,0,0,0}, aZ[4]={0,0,0,0}, aNX[4]={0,0,0,0}, aNH[4]={0,0,0,0};
  {
    int k0 = kq*64;
    #pragma unroll 4
    for (int k = k0; k < k0+64; k += 4){
      float4 xv = *(const float4*)(x + k);
      #pragma unroll
      for (int jj = 0; jj < 4; jj++){
        aR[jj]  += dot4(xv, *(const float4*)&sWi[(    jj)*INP + k]);
        aZ[jj]  += dot4(xv, *(const float4*)&sWi[(4 + jj)*INP + k]);
        aNX[jj] += dot4(xv, *(const float4*)&sWi[(8 + jj)*INP + k]);
      }
    }
  }
  {
    int k0 = kq*128;
    #pragma unroll 4
    for (int k = k0; k < k0+128; k += 4){
      float4 hv = *(const float4*)(h + k);
      #pragma unroll
      for (int jj = 0; jj < 4; jj++){
        aR[jj]  += dot4(hv, *(const float4*)&sWh[(    jj)*HH + k]);
        aZ[jj]  += dot4(hv, *(const float4*)&sWh[(4 + jj)*HH + k]);
        aNH[jj] += dot4(hv, *(const float4*)&sWh[(8 + jj)*HH + k]);
      }
    }
  }
  __syncthreads();                          // all weight reads done
  float* sP = sbuf;                         // overlay: 16 x 512 partials
  #pragma unroll
  for (int jj = 0; jj < 4; jj++){
    sP[( 0 + jj)*512 + tid] = aR[jj];
    sP[( 4 + jj)*512 + tid] = aZ[jj];
    sP[( 8 + jj)*512 + tid] = aNX[jj];
    sP[(12 + jj)*512 + tid] = aNH[jj];
  }
  __syncthreads();
  if (tid < 128){
    int bb = tid;
    bool act = t < src_len[bb];
    const float* hb = hin + bb*HH;
    #pragma unroll
    for (int jj = 0; jj < 4; jj++){
      float vR  = ((sP[( 0+jj)*512+bb] + sP[( 0+jj)*512+bb+128])
                 + (sP[( 0+jj)*512+bb+256] + sP[( 0+jj)*512+bb+384]));
      float vZ  = ((sP[( 4+jj)*512+bb] + sP[( 4+jj)*512+bb+128])
                 + (sP[( 4+jj)*512+bb+256] + sP[( 4+jj)*512+bb+384]));
      float vNX = ((sP[( 8+jj)*512+bb] + sP[( 8+jj)*512+bb+128])
                 + (sP[( 8+jj)*512+bb+256] + sP[( 8+jj)*512+bb+384]));
      float vNH = ((sP[(12+jj)*512+bb] + sP[(12+jj)*512+bb+128])
                 + (sP[(12+jj)*512+bb+256] + sP[(12+jj)*512+bb+384]));
      int j = j0 + jj;
      float r = sigf(vR + bi[j]      + bh[j]);
      float z = sigf(vZ + bi[HH+j]   + bh[HH+j]);
      float n = tanhf(vNX + bi[2*HH+j] + r*(vNH + bh[2*HH+j]));
      float hv = (1.f - z)*n + z*hb[j];
      hout[bb*HH + j] = act ? hv : hb[j];
    }
  }
}

// ---------------- decoder GRU step (k-split x4, 512 threads, R10) ------------
__global__ __launch_bounds__(512) void k_dec_gru(
  const float* __restrict__ emb,
  const float* __restrict__ Wi, const float* __restrict__ Wh,
  const float* __restrict__ bi, const float* __restrict__ bh, int i)
{
  __shared__ float sbuf[12*260 + 12*HH];   // 37KB; overlay sP[16*512]
  float* sWi = sbuf;                        // 12 rows x 260 (257 padded)
  float* sWh = sbuf + 12*260;
  const float* hin  = (i & 1) ? g_hB : g_hA;
  float*       hout = (i & 1) ? g_hA : g_hB;
  int j0 = blockIdx.x * 4;
  int tid = threadIdx.x;
  int b = tid & 127, kq = tid >> 7;
  for (int p = tid; p < 12*257; p += 512){
    int r = p / 257, c = p - r*257;
    int g = r >> 2, jj = r & 3;
    sWi[r*260 + c] = Wi[(g*HH + j0 + jj)*257 + c];
  }
  for (int p = tid; p < 12*(HH/4); p += 512){
    int r = p >> 7, c4 = p & 127;
    int g = r >> 2, jj = r & 3;
    ((float4*)sWh)[p] = ((const float4*)(Wh + (g*HH + j0 + jj)*HH))[c4];
  }
  __syncthreads();
  const float* xe = emb + (long)g_eid[b]*EE;
  const float* h = hin + b*HH;
  float aR[4]={0,0,0,0}, aZ[4]={0,0,0,0}, aNX[4]={0,0,0,0}, aNH[4]={0,0,0,0};
  {
    int k0 = kq*64;
    #pragma unroll 4
    for (int k = k0; k < k0+64; k += 4){
      float4 xv = *(const float4*)(xe + k);
      #pragma unroll
      for (int jj = 0; jj < 4; jj++){
        aR[jj]  += dot4(xv, *(const float4*)&sWi[(    jj)*260 + k]);
        aZ[jj]  += dot4(xv, *(const float4*)&sWi[(4 + jj)*260 + k]);
        aNX[jj] += dot4(xv, *(const float4*)&sWi[(8 + jj)*260 + k]);
      }
    }
  }
  if (kq == 0){                             // rate column (k = 256)
    float rate = g_rate[b];
    #pragma unroll
    for (int jj = 0; jj < 4; jj++){
      aR[jj]  += rate * sWi[(    jj)*260 + 256];
      aZ[jj]  += rate * sWi[(4 + jj)*260 + 256];
      aNX[jj] += rate * sWi[(8 + jj)*260 + 256];
    }
  }
  {
    int k0 = kq*128;
    #pragma unroll 4
    for (int k = k0; k < k0+128; k += 4){
      float4 hv = *(const float4*)(h + k);
      #pragma unroll
      for (int jj = 0; jj < 4; jj++){
        aR[jj]  += dot4(hv, *(const float4*)&sWh[(    jj)*HH + k]);
        aZ[jj]  += dot4(hv, *(const float4*)&sWh[(4 + jj)*HH + k]);
        aNH[jj] += dot4(hv, *(const float4*)&sWh[(8 + jj)*HH + k]);
      }
    }
  }
  __syncthreads();
  float* sP = sbuf;
  #pragma unroll
  for (int jj = 0; jj < 4; jj++){
    sP[( 0 + jj)*512 + tid] = aR[jj];
    sP[( 4 + jj)*512 + tid] = aZ[jj];
    sP[( 8 + jj)*512 + tid] = aNX[jj];
    sP[(12 + jj)*512 + tid] = aNH[jj];
  }
  __syncthreads();
  if (tid < 128){
    int bb = tid;
    const float* hb = hin + bb*HH;
    #pragma unroll
    for (int jj = 0; jj < 4; jj++){
      float vR  = ((sP[( 0+jj)*512+bb] + sP[( 0+jj)*512+bb+128])
                 + (sP[( 0+jj)*512+bb+256] + sP[( 0+jj)*512+bb+384]));
      float vZ  = ((sP[( 4+jj)*512+bb] + sP[( 4+jj)*512+bb+128])
                 + (sP[( 4+jj)*512+bb+256] + sP[( 4+jj)*512+bb+384]));
      float vNX = ((sP[( 8+jj)*512+bb] + sP[( 8+jj)*512+bb+128])
                 + (sP[( 8+jj)*512+bb+256] + sP[( 8+jj)*512+bb+384]));
      float vNH = ((sP[(12+jj)*512+bb] + sP[(12+jj)*512+bb+128])
                 + (sP[(12+jj)*512+bb+256] + sP[(12+jj)*512+bb+384]));
      int j = j0 + jj;
      float r = sigf(vR + bi[j]      + bh[j]);
      float z = sigf(vZ + bi[HH+j]   + bh[HH+j]);
      float n = tanhf(vNX + bi[2*HH+j] + r*(vNH + bh[2*HH+j]));
      hout[bb*HH + j] = (1.f - z)*n + z*hb[j];
    }
  }
}

// ---------------- logits GEMM: out[s] = h @ We^T + be (raw logits) -----------
// BM=128, BN=48, BK=32, 192 threads (ty=16 x 8 rows, tx=12 x 4 cols), occ 3.
// R11 version (estimated ~88us/step vs 104 at BN=64).
__global__ __launch_bounds__(192, 3) void k_logits(
  const float* __restrict__ We, const float* __restrict__ be,
  float* __restrict__ out, int i, int s)
{
  __shared__ float sA[BK_L*SA_STRIDE];     // 16.9KB
  __shared__ float sB[BK_L*SB_STRIDE];     // 6.7KB
  const float* h = (i & 1) ? g_hA : g_hB;
  int tile = blockIdx.x;
  int n0 = tile * BN_L;
  int t = threadIdx.x;
  int tx = t % 12, ty = t / 12;            // ty in 0..15
  float acc[8][4];
  #pragma unroll
  for (int a = 0; a < 8; a++)
    #pragma unroll
    for (int c = 0; c < 4; c++) acc[a][c] = 0.f;

  for (int k0 = 0; k0 < HH; k0 += BK_L){
    for (int p = t; p < 1024; p += 192){          // A tile: 128x32 (transpose)
      int row = p >> 3, c4 = p & 7;
      float4 v = *(const float4*)(h + row*HH + k0 + c4*4);
      sA[(c4*4+0)*SA_STRIDE + row] = v.x;
      sA[(c4*4+1)*SA_STRIDE + row] = v.y;
      sA[(c4*4+2)*SA_STRIDE + row] = v.z;
      sA[(c4*4+3)*SA_STRIDE + row] = v.w;
    }
    for (int p = t; p < 384; p += 192){           // B tile: 48x32 (transpose)
      int row = p >> 3, c4 = p & 7;
      int n = n0 + row; if (n >= VV) n = 0;       // clamp (discarded later)
      float4 v = *(const float4*)(We + (long)n*HH + k0 + c4*4);
      sB[(c4*4+0)*SB_STRIDE + row] = v.x;
      sB[(c4*4+1)*SB_STRIDE + row] = v.y;
      sB[(c4*4+2)*SB_STRIDE + row] = v.z;
      sB[(c4*4+3)*SB_STRIDE + row] = v.w;
    }
    __syncthreads();
    float loc[8][4];
    #pragma unroll
    for (int a = 0; a < 8; a++)
      #pragma unroll
      for (int c = 0; c < 4; c++) loc[a][c] = 0.f;
    #pragma unroll
    for (int kk = 0; kk < BK_L; kk++){
      float4 a01 = *(const float4*)&sA[kk*SA_STRIDE + ty*8];
      float4 a23 = *(const float4*)&sA[kk*SA_STRIDE + ty*8 + 4];
      float4 bv  = *(const float4*)&sB[kk*SB_STRIDE + tx*4];
      float a[8] = {a01.x,a01.y,a01.z,a01.w,a23.x,a23.y,a23.z,a23.w};
      float bf[4] = {bv.x,bv.y,bv.z,bv.w};
      #pragma unroll
      for (int ii = 0; ii < 8; ii++)
        #pragma unroll
        for (int jj = 0; jj < 4; jj++) loc[ii][jj] += a[ii]*bf[jj];
    }
    #pragma unroll
    for (int ii = 0; ii < 8; ii++)
      #pragma unroll
      for (int jj = 0; jj < 4; jj++)
        acc[ii][jj] = __fadd_rn(acc[ii][jj], loc[ii][jj]);
    __syncthreads();
  }

  // epilogue: bias, store raw logits to out, per-(tile,row) max/sumexp
  float bias[4];
  #pragma unroll
  for (int jj = 0; jj < 4; jj++){
    int n = n0 + tx*4 + jj;
    bias[jj] = (n < VV) ? be[n] : 0.f;
  }
  int nbase = n0 + tx*4;
  bool fullvec = (nbase + 3 < VV);
  float* sM = sA;                   // overlay: 12 x 128 max
  float* sS = sA + 12*128;          // overlay: 12 x 128 sumexp
  float* orow = out + (long)s*BB*VV;
  #pragma unroll
  for (int ii = 0; ii < 8; ii++){
    int r = ty*8 + ii;
    float vals[4];
    float m = -3.402823466e38f;
    bool anyv = false;
    #pragma unroll
    for (int jj = 0; jj < 4; jj++){
      int n = nbase + jj;
      float v = acc[ii][jj] + bias[jj];
      vals[jj] = v;
      if (n < VV){ anyv = true; if (v > m) m = v; }
    }
    float ss = 0.f;
    if (anyv){
      #pragma unroll
      for (int jj = 0; jj < 4; jj++){
        int n = nbase + jj;
        if (n < VV) ss += __expf(vals[jj] - m);
      }
    }
    if (fullvec){
      *(float4*)&orow[(long)r*VV + nbase] = make_float4(vals[0],vals[1],vals[2],vals[3]);
    } else {
      #pragma unroll
      for (int jj = 0; jj < 4; jj++){
        int n = nbase + jj;
        if (n < VV) orow[(long)r*VV + n] = vals[jj];
      }
    }
    sM[tx*128 + r] = m;
    sS[tx*128 + r] = ss;
  }
  __syncthreads();
  if (t < 128){
    int r = t;
    float m = -3.402823466e38f, ss = 0.f;
    #pragma unroll
    for (int q = 0; q < 12; q++)
      merge2(m, ss, sM[q*128 + r], sS[q*128 + r]);
    g_pmax[r*NT_L + tile] = m;
    g_psum[r*NT_L + tile] = ss;
  }
}

// ---------------- fused: row reduce + in-place logp + argmax -----------------
// Per block = one batch row. Reduces 417 tile partials to (m, ls), then
// rewrites out[s,b,:] in place: logp = fl(fl(x - m) - ls), and argmaxes the
// ROUNDED values, first-index ties (matches jnp.argmax(log_softmax(x))).
__global__ __launch_bounds__(512) void k_write(float* __restrict__ out, int s)
{
  int b = blockIdx.x, t = threadIdx.x;
  __shared__ float sm[512]; __shared__ float ssm[512];
  float m = -3.402823466e38f; float ssum = 0.f;
  for (int tile = t; tile < NT_L; tile += 512)
    merge2(m, ssum, g_pmax[b*NT_L+tile], g_psum[b*NT_L+tile]);
  sm[t] = m; ssm[t] = ssum;
  __syncthreads();
  for (int off = 256; off; off >>= 1){
    if (t < off){
      float m2 = sm[t]; float s2 = ssm[t];
      merge2(m2, s2, sm[t+off], ssm[t+off]);
      sm[t] = m2; ssm[t] = s2;
    }
    __syncthreads();
  }
  m = sm[0];
  float ls = logf(ssm[0]);
  __syncthreads();

  float4* rowp = (float4*)(out + (long)s*BB*VV + (long)b*VV);
  float bm = -3.402823466e38f; int bi_ = 0x7fffffff;
  for (int p = t; p < VV/4; p += 512){
    float4 v = rowp[p];
    float r0 = __fsub_rn(__fsub_rn(v.x, m), ls);
    float r1 = __fsub_rn(__fsub_rn(v.y, m), ls);
    float r2 = __fsub_rn(__fsub_rn(v.z, m), ls);
    float r3 = __fsub_rn(__fsub_rn(v.w, m), ls);
    rowp[p] = make_float4(r0, r1, r2, r3);
    int n = p*4;   // ascending + strictly-greater => thread-local first idx
    if (r0 > bm){ bm = r0; bi_ = n;     }
    if (r1 > bm){ bm = r1; bi_ = n + 1; }
    if (r2 > bm){ bm = r2; bi_ = n + 2; }
    if (r3 > bm){ bm = r3; bi_ = n + 3; }
  }
  __shared__ float sv[512]; __shared__ int si[512];
  sv[t] = bm; si[t] = bi_;
  __syncthreads();
  for (int off = 256; off; off >>= 1){
    if (t < off){
      float ov = sv[t+off]; int oi = si[t+off];
      if (ov > sv[t] || (ov == sv[t] && oi < si[t])){ sv[t] = ov; si[t] = oi; }
    }
    __syncthreads();
  }
  if (t == 0) g_eid[b] = si[0];
}

// ---------------- fused rate head: pr = sig(relu([emb;h]W1^T+b1)W2^T+b2) -----
// One block per batch row, 256 threads. Each thread computes 2 of the 512
// pr1 units (full 768-K dot from gmem/L2), relu, multiplies by W2, then a
// block reduction produces pr. Removes the k_pr1/k_pr2 split + g_ph traffic.
__global__ __launch_bounds__(256) void k_pr(
  const float* __restrict__ emb, const float* __restrict__ W1,
  const float* __restrict__ b1,  const float* __restrict__ W2,
  const float* __restrict__ b2,  float* __restrict__ out, int i, int s)
{
  const float* h = (i & 1) ? g_hA : g_hB;
  int b = blockIdx.x, t = threadIdx.x;
  __shared__ float sx[768+4];               // [emb[eid] | h(b)]
  int eid = g_eid[b];
  const float* xe = emb + (long)eid*EE;
  for (int k = t; k < EE/4; k += 256) ((float4*)sx)[k] = ((const float4*)xe)[k];
  for (int k = t; k < HH/4; k += 256)
    ((float4*)(sx+EE))[k] = ((const float4*)(h + b*HH))[k];
  __syncthreads();
  float part = 0.f;
  #pragma unroll
  for (int u = 0; u < 2; u++){
    int j = t*2 + u;                        // pr1 unit
    const float* w = W1 + j*768;
    float acc = 0.f;
    #pragma unroll 4
    for (int k = 0; k < 768; k += 4)
      acc += dot4(*(const float4*)(sx + k), *(const float4*)(w + k));
    part += fmaxf(acc + b1[j], 0.f) * W2[j];
  }
  __shared__ float red[256];
  red[t] = part;
  __syncthreads();
  for (int off = 128; off; off >>= 1){
    if (t < off) red[t] = __fadd_rn(red[t], red[t+off]);
    __syncthreads();
  }
  if (t == 0){
    float pr = sigf(red[0] + b2[0]);
    out[(long)TTRG*BB*VV + (long)s*BB + b] = pr;
    g_rate[b] = pr;
  }
}

// ---------------- host driver ------------------------------------------------
extern "C" void kernel_launch(void* const* d_in, const int* in_sizes, int n_in,
                              void* d_out, int out_size)
{
  (void)in_sizes; (void)n_in; (void)out_size;
  const float* src      = (const float*)d_in[0];
  const int*   src_len  = (const int*)  d_in[1];
  const int*   trg_eid  = (const int*)  d_in[2];
  const float* trg_rate = (const float*)d_in[3];
  const float* emb      = (const float*)d_in[4];
  const float* enc_Wi   = (const float*)d_in[5];
  const float* enc_Wh   = (const float*)d_in[6];
  const float* enc_bi   = (const float*)d_in[7];
  const float* enc_bh   = (const float*)d_in[8];
  const float* dec_Wi   = (const float*)d_in[9];
  const float* dec_Wh   = (const float*)d_in[10];
  const float* dec_bi   = (const float*)d_in[11];
  const float* dec_bh   = (const float*)d_in[12];
  const float* We       = (const float*)d_in[13];
  const float* be       = (const float*)d_in[14];
  const float* W1       = (const float*)d_in[15];
  const float* b1       = (const float*)d_in[16];
  const float* W2       = (const float*)d_in[17];
  const float* b2       = (const float*)d_in[18];
  float* out = (float*)d_out;

  k_init<<<2560, 256>>>(trg_eid, trg_rate, out);

  // ---- encoder: 64 sequential GRU steps (h ping-pongs A<->B, ends in A)
  for (int t = 0; t < TSRC; t++)
    k_enc<<<128, 512>>>(src, src_len, enc_Wi, enc_Wh, enc_bi, enc_bh, t);

  // ---- decoder: 49 sequential steps, output index s = i+1
  for (int i = 0; i < TTRG - 1; i++){
    k_dec_gru<<<128, 512>>>(emb, dec_Wi, dec_Wh, dec_bi, dec_bh, i);
    k_logits<<<NT_L, 192>>>(We, be, out, i, i + 1);   // raw logits -> out[s]
    k_write<<<128, 512>>>(out, i + 1);                // reduce + logp + argmax
    k_pr<<<128, 256>>>(emb, W1, b1, W2, b2, out, i, i + 1);
  }
}

// round 13
// speedup vs baseline: 1.1116x; 1.1037x over previous
#include <cuda_runtime.h>
#include <math.h>
#include <stdint.h>

#define BB   128
#define HH   512
#define INP  256
#define EE   256
#define VV   20000
#define TSRC 64
#define TTRG 50

// logits GEMM tiling (tensor core): BM=128, BN=64, 313 tiles
#define BN_L 64
#define NT_L 313          // ceil(20000/64)
#define AST  36           // sA row stride (floats): conflict-free frag loads
#define BST  36           // sB row stride

// ---------------- persistent device scratch (no allocations) ----------------
__device__ float g_hA[BB*HH];
__device__ float g_hB[BB*HH];
__device__ float g_pmax[BB*NT_L];
__device__ float g_psum[BB*NT_L];
__device__ int   g_eid[BB];                // decoder carry: token id
__device__ float g_rate[BB];               // decoder carry: rate
__device__ float g_ph[BB*HH];              // relu(pr1)

__device__ __forceinline__ float sigf(float x){ return 1.f/(1.f+expf(-x)); }
__device__ __forceinline__ float dot4(float4 a, float4 b){
  return a.x*b.x + a.y*b.y + a.z*b.z + a.w*b.w;
}
// merge (max-value, sum-of-exp-relative-to-max). Safe with -FLT_MAX sentinel.
__device__ __forceinline__ void merge2(float& m, float& s, float om, float os){
  if (om > m){ s = s*__expf(m-om) + os; m = om; }
  else       { s = s + os*__expf(om-m); }
}
// split fp32 into two tf32 values (hi + lo); 4-product MMA recovers fp32-class
__device__ __forceinline__ void split_tf32(float x, uint32_t& hi, uint32_t& lo){
  uint32_t h_; asm("cvt.rna.tf32.f32 %0, %1;" : "=r"(h_) : "f"(x));
  float l = __fsub_rn(x, __uint_as_float(h_));
  asm("cvt.rna.tf32.f32 %0, %1;" : "=r"(lo) : "f"(l));
  hi = h_;
}
__device__ __forceinline__ void mma8(float* d,
  uint32_t a0,uint32_t a1,uint32_t a2,uint32_t a3, uint32_t b0,uint32_t b1){
  asm volatile("mma.sync.aligned.m16n8k8.row.col.f32.tf32.tf32.f32 "
    "{%0,%1,%2,%3}, {%4,%5,%6,%7}, {%8,%9}, {%0,%1,%2,%3};"
    : "+f"(d[0]),"+f"(d[1]),"+f"(d[2]),"+f"(d[3])
    : "r"(a0),"r"(a1),"r"(a2),"r"(a3),"r"(b0),"r"(b1));
}

// ---------------- init: zero step-0 outputs, h0, seed decoder carry ----------
__global__ void k_init(const int* __restrict__ trg_eid,
                       const float* __restrict__ trg_rate,
                       float* __restrict__ out)
{
  long idx = (long)blockIdx.x*blockDim.x + threadIdx.x;
  const long NZ = (long)BB*VV/4;               // 640000 float4
  float4 z = make_float4(0.f,0.f,0.f,0.f);
  if (idx < NZ) ((float4*)out)[idx] = z;       // eid_result[0] = 0
  if (idx < BB*HH/4) ((float4*)g_hA)[idx] = z; // h0 = 0
  if (idx < BB) {
    out[(long)TTRG*BB*VV + idx] = 0.f;         // rate_result[0] = 0
    g_eid[idx]  = trg_eid[idx];                // trg_eid[0, b]
    g_rate[idx] = trg_rate[idx];               // trg_rate[0, b]
  }
}

// ---------------- encoder GRU step (k-split x4, 512 threads, R10) ------------
__global__ __launch_bounds__(512) void k_enc(
  const float* __restrict__ src, const int* __restrict__ src_len,
  const float* __restrict__ Wi, const float* __restrict__ Wh,
  const float* __restrict__ bi, const float* __restrict__ bh, int t)
{
  __shared__ float sbuf[12*INP + 12*HH];   // 36KB; later overlaid by sP[16*512]
  float* sWi = sbuf;                        // 12 rows x INP
  float* sWh = sbuf + 12*INP;               // 12 rows x HH
  const float* hin  = (t & 1) ? g_hB : g_hA;
  float*       hout = (t & 1) ? g_hA : g_hB;
  int j0 = blockIdx.x * 4;
  int tid = threadIdx.x;
  int b = tid & 127, kq = tid >> 7;
  for (int p = tid; p < 12*(INP/4); p += 512){
    int r = p >> 6, c4 = p & 63;
    int g = r >> 2, jj = r & 3;
    ((float4*)sWi)[p] = ((const float4*)(Wi + (g*HH + j0 + jj)*INP))[c4];
  }
  for (int p = tid; p < 12*(HH/4); p += 512){
    int r = p >> 7, c4 = p & 127;
    int g = r >> 2, jj = r & 3;
    ((float4*)sWh)[p] = ((const float4*)(Wh + (g*HH + j0 + jj)*HH))[c4];
  }
  __syncthreads();
  const float* x = src + ((long)t*BB + b)*INP;
  const float* h = hin + b*HH;
  float aR[4]={0,0,0,0}, aZ[4]={0,0,0,0}, aNX[4]={0,0,0,0}, aNH[4]={0,0,0,0};
  {
    int k0 = kq*64;
    #pragma unroll 4
    for (int k = k0; k < k0+64; k += 4){
      float4 xv = *(const float4*)(x + k);
      #pragma unroll
      for (int jj = 0; jj < 4; jj++){
        aR[jj]  += dot4(xv, *(const float4*)&sWi[(    jj)*INP + k]);
        aZ[jj]  += dot4(xv, *(const float4*)&sWi[(4 + jj)*INP + k]);
        aNX[jj] += dot4(xv, *(const float4*)&sWi[(8 + jj)*INP + k]);
      }
    }
  }
  {
    int k0 = kq*128;
    #pragma unroll 4
    for (int k = k0; k < k0+128; k += 4){
      float4 hv = *(const float4*)(h + k);
      #pragma unroll
      for (int jj = 0; jj < 4; jj++){
        aR[jj]  += dot4(hv, *(const float4*)&sWh[(    jj)*HH + k]);
        aZ[jj]  += dot4(hv, *(const float4*)&sWh[(4 + jj)*HH + k]);
        aNH[jj] += dot4(hv, *(const float4*)&sWh[(8 + jj)*HH + k]);
      }
    }
  }
  __syncthreads();                          // all weight reads done
  float* sP = sbuf;                         // overlay: 16 x 512 partials
  #pragma unroll
  for (int jj = 0; jj < 4; jj++){
    sP[( 0 + jj)*512 + tid] = aR[jj];
    sP[( 4 + jj)*512 + tid] = aZ[jj];
    sP[( 8 + jj)*512 + tid] = aNX[jj];
    sP[(12 + jj)*512 + tid] = aNH[jj];
  }
  __syncthreads();
  if (tid < 128){
    int bb = tid;
    bool act = t < src_len[bb];
    const float* hb = hin + bb*HH;
    #pragma unroll
    for (int jj = 0; jj < 4; jj++){
      float vR  = ((sP[( 0+jj)*512+bb] + sP[( 0+jj)*512+bb+128])
                 + (sP[( 0+jj)*512+bb+256] + sP[( 0+jj)*512+bb+384]));
      float vZ  = ((sP[( 4+jj)*512+bb] + sP[( 4+jj)*512+bb+128])
                 + (sP[( 4+jj)*512+bb+256] + sP[( 4+jj)*512+bb+384]));
      float vNX = ((sP[( 8+jj)*512+bb] + sP[( 8+jj)*512+bb+128])
                 + (sP[( 8+jj)*512+bb+256] + sP[( 8+jj)*512+bb+384]));
      float vNH = ((sP[(12+jj)*512+bb] + sP[(12+jj)*512+bb+128])
                 + (sP[(12+jj)*512+bb+256] + sP[(12+jj)*512+bb+384]));
      int j = j0 + jj;
      float r = sigf(vR + bi[j]      + bh[j]);
      float z = sigf(vZ + bi[HH+j]   + bh[HH+j]);
      float n = tanhf(vNX + bi[2*HH+j] + r*(vNH + bh[2*HH+j]));
      float hv = (1.f - z)*n + z*hb[j];
      hout[bb*HH + j] = act ? hv : hb[j];
    }
  }
}

// ---------------- decoder GRU step (k-split x4, 512 threads, R10) ------------
__global__ __launch_bounds__(512) void k_dec_gru(
  const float* __restrict__ emb,
  const float* __restrict__ Wi, const float* __restrict__ Wh,
  const float* __restrict__ bi, const float* __restrict__ bh, int i)
{
  __shared__ float sbuf[12*260 + 12*HH];   // 37KB; overlay sP[16*512]
  float* sWi = sbuf;                        // 12 rows x 260 (257 padded)
  float* sWh = sbuf + 12*260;
  const float* hin  = (i & 1) ? g_hB : g_hA;
  float*       hout = (i & 1) ? g_hA : g_hB;
  int j0 = blockIdx.x * 4;
  int tid = threadIdx.x;
  int b = tid & 127, kq = tid >> 7;
  for (int p = tid; p < 12*257; p += 512){
    int r = p / 257, c = p - r*257;
    int g = r >> 2, jj = r & 3;
    sWi[r*260 + c] = Wi[(g*HH + j0 + jj)*257 + c];
  }
  for (int p = tid; p < 12*(HH/4); p += 512){
    int r = p >> 7, c4 = p & 127;
    int g = r >> 2, jj = r & 3;
    ((float4*)sWh)[p] = ((const float4*)(Wh + (g*HH + j0 + jj)*HH))[c4];
  }
  __syncthreads();
  const float* xe = emb + (long)g_eid[b]*EE;
  const float* h = hin + b*HH;
  float aR[4]={0,0,0,0}, aZ[4]={0,0,0,0}, aNX[4]={0,0,0,0}, aNH[4]={0,0,0,0};
  {
    int k0 = kq*64;
    #pragma unroll 4
    for (int k = k0; k < k0+64; k += 4){
      float4 xv = *(const float4*)(xe + k);
      #pragma unroll
      for (int jj = 0; jj < 4; jj++){
        aR[jj]  += dot4(xv, *(const float4*)&sWi[(    jj)*260 + k]);
        aZ[jj]  += dot4(xv, *(const float4*)&sWi[(4 + jj)*260 + k]);
        aNX[jj] += dot4(xv, *(const float4*)&sWi[(8 + jj)*260 + k]);
      }
    }
  }
  if (kq == 0){                             // rate column (k = 256)
    float rate = g_rate[b];
    #pragma unroll
    for (int jj = 0; jj < 4; jj++){
      aR[jj]  += rate * sWi[(    jj)*260 + 256];
      aZ[jj]  += rate * sWi[(4 + jj)*260 + 256];
      aNX[jj] += rate * sWi[(8 + jj)*260 + 256];
    }
  }
  {
    int k0 = kq*128;
    #pragma unroll 4
    for (int k = k0; k < k0+128; k += 4){
      float4 hv = *(const float4*)(h + k);
      #pragma unroll
      for (int jj = 0; jj < 4; jj++){
        aR[jj]  += dot4(hv, *(const float4*)&sWh[(    jj)*HH + k]);
        aZ[jj]  += dot4(hv, *(const float4*)&sWh[(4 + jj)*HH + k]);
        aNH[jj] += dot4(hv, *(const float4*)&sWh[(8 + jj)*HH + k]);
      }
    }
  }
  __syncthreads();
  float* sP = sbuf;
  #pragma unroll
  for (int jj = 0; jj < 4; jj++){
    sP[( 0 + jj)*512 + tid] = aR[jj];
    sP[( 4 + jj)*512 + tid] = aZ[jj];
    sP[( 8 + jj)*512 + tid] = aNX[jj];
    sP[(12 + jj)*512 + tid] = aNH[jj];
  }
  __syncthreads();
  if (tid < 128){
    int bb = tid;
    const float* hb = hin + bb*HH;
    #pragma unroll
    for (int jj = 0; jj < 4; jj++){
      float vR  = ((sP[( 0+jj)*512+bb] + sP[( 0+jj)*512+bb+128])
                 + (sP[( 0+jj)*512+bb+256] + sP[( 0+jj)*512+bb+384]));
      float vZ  = ((sP[( 4+jj)*512+bb] + sP[( 4+jj)*512+bb+128])
                 + (sP[( 4+jj)*512+bb+256] + sP[( 4+jj)*512+bb+384]));
      float vNX = ((sP[( 8+jj)*512+bb] + sP[( 8+jj)*512+bb+128])
                 + (sP[( 8+jj)*512+bb+256] + sP[( 8+jj)*512+bb+384]));
      float vNH = ((sP[(12+jj)*512+bb] + sP[(12+jj)*512+bb+128])
                 + (sP[(12+jj)*512+bb+256] + sP[(12+jj)*512+bb+384]));
      int j = j0 + jj;
      float r = sigf(vR + bi[j]      + bh[j]);
      float z = sigf(vZ + bi[HH+j]   + bh[HH+j]);
      float n = tanhf(vNX + bi[2*HH+j] + r*(vNH + bh[2*HH+j]));
      hout[bb*HH + j] = (1.f - z)*n + z*hb[j];
    }
  }
}

// ---------------- logits GEMM via 4xTF32 tensor cores ------------------------
// C[128,64/tile] = h @ We^T + be. 256 threads = 8 warps (4M x 2N), warp tile
// 32x32 (2 m16 x 4 n8). Each fp32 operand split hi+lo (tf32); all 4 products
// accumulated => fp32-class precision. Raw logits -> out[s]; per-tile
// max/sumexp partials -> g_pmax/g_psum (reduced in k_write).
__global__ __launch_bounds__(256) void k_logits(
  const float* __restrict__ We, const float* __restrict__ be,
  float* __restrict__ out, int i, int s)
{
  __shared__ float sA[128*AST];             // 18.4KB  h tile [m][k], stride 36
  __shared__ float sB[64*BST];              // 9.2KB   We tile [n][k], stride 36
  __shared__ float sM[2*128], sS[2*128];    // per-warp_n row stats
  const float* h = (i & 1) ? g_hA : g_hB;
  int tile = blockIdx.x;
  int n0 = tile * BN_L;
  int t = threadIdx.x;
  int lane = t & 31, wid = t >> 5;
  int gid = lane >> 2, tig = lane & 3;
  int warp_m = wid >> 1, warp_n = wid & 1;

  float acc[2][4][4];
  #pragma unroll
  for (int mt = 0; mt < 2; mt++)
    #pragma unroll
    for (int nt = 0; nt < 4; nt++)
      #pragma unroll
      for (int q = 0; q < 4; q++) acc[mt][nt][q] = 0.f;

  for (int k0 = 0; k0 < HH; k0 += 32){
    #pragma unroll
    for (int ld = 0; ld < 4; ld++){         // A: 128 rows x 32 k (1024 float4)
      int p = t + ld*256;
      int row = p >> 3, c4 = p & 7;
      float4 v = *(const float4*)(h + row*HH + k0 + c4*4);
      *(float4*)&sA[row*AST + c4*4] = v;
    }
    #pragma unroll
    for (int ld = 0; ld < 2; ld++){         // B: 64 n-rows x 32 k (512 float4)
      int p = t + ld*256;
      int n = p >> 3, c4 = p & 7;
      int nn = n0 + n; if (nn >= VV) nn = 0;   // clamp; discarded in epilogue
      float4 v = *(const float4*)(We + (long)nn*HH + k0 + c4*4);
      *(float4*)&sB[n*BST + c4*4] = v;
    }
    __syncthreads();
    #pragma unroll
    for (int kk = 0; kk < 32; kk += 8){
      uint32_t Ah[2][4], Al[2][4];
      #pragma unroll
      for (int mt = 0; mt < 2; mt++){
        int rb = warp_m*32 + mt*16 + gid;
        split_tf32(sA[(rb    )*AST + kk + tig    ], Ah[mt][0], Al[mt][0]);
        split_tf32(sA[(rb + 8)*AST + kk + tig    ], Ah[mt][1], Al[mt][1]);
        split_tf32(sA[(rb    )*AST + kk + tig + 4], Ah[mt][2], Al[mt][2]);
        split_tf32(sA[(rb + 8)*AST + kk + tig + 4], Ah[mt][3], Al[mt][3]);
      }
      uint32_t Bh[4][2], Bl[4][2];
      #pragma unroll
      for (int nt = 0; nt < 4; nt++){
        int nb = warp_n*32 + nt*8 + gid;
        split_tf32(sB[nb*BST + kk + tig    ], Bh[nt][0], Bl[nt][0]);
        split_tf32(sB[nb*BST + kk + tig + 4], Bh[nt][1], Bl[nt][1]);
      }
      #pragma unroll
      for (int mt = 0; mt < 2; mt++)
        #pragma unroll
        for (int nt = 0; nt < 4; nt++){
          float* d = acc[mt][nt];
          mma8(d, Al[mt][0],Al[mt][1],Al[mt][2],Al[mt][3], Bl[nt][0],Bl[nt][1]);
          mma8(d, Ah[mt][0],Ah[mt][1],Ah[mt][2],Ah[mt][3], Bl[nt][0],Bl[nt][1]);
          mma8(d, Al[mt][0],Al[mt][1],Al[mt][2],Al[mt][3], Bh[nt][0],Bh[nt][1]);
          mma8(d, Ah[mt][0],Ah[mt][1],Ah[mt][2],Ah[mt][3], Bh[nt][0],Bh[nt][1]);
        }
    }
    __syncthreads();
  }

  // ---- epilogue: bias, store raw logits, per-row stats ----
  float* orow = out + (long)s*BB*VV;
  #pragma unroll
  for (int mt = 0; mt < 2; mt++){
    int r0 = warp_m*32 + mt*16 + gid;
    int r1 = r0 + 8;
    float m0 = -3.402823466e38f, s0 = 0.f;
    float m1 = -3.402823466e38f, s1 = 0.f;
    #pragma unroll
    for (int nt = 0; nt < 4; nt++){
      int c0 = n0 + warp_n*32 + nt*8 + tig*2;
      bool ok0 = (c0     < VV);
      bool ok1 = (c0 + 1 < VV);
      float b0v = ok0 ? be[c0]   : 0.f;
      float b1v = ok1 ? be[c0+1] : 0.f;
      float x00 = acc[mt][nt][0] + b0v;   // (r0, c0)
      float x01 = acc[mt][nt][1] + b1v;   // (r0, c0+1)
      float x10 = acc[mt][nt][2] + b0v;   // (r1, c0)
      float x11 = acc[mt][nt][3] + b1v;   // (r1, c0+1)
      if (ok0 && ok1){
        *(float2*)&orow[(long)r0*VV + c0] = make_float2(x00, x01);
        *(float2*)&orow[(long)r1*VV + c0] = make_float2(x10, x11);
      } else {
        if (ok0){ orow[(long)r0*VV + c0] = x00; orow[(long)r1*VV + c0] = x10; }
        if (ok1){ orow[(long)r0*VV + c0+1] = x01; orow[(long)r1*VV + c0+1] = x11; }
      }
      // stats (valid cols only)
      if (ok0){ merge2(m0, s0, x00, 1.f); merge2(m1, s1, x10, 1.f); }
      if (ok1){ merge2(m0, s0, x01, 1.f); merge2(m1, s1, x11, 1.f); }
    }
    // quad reduce across tig lanes (same gid => same rows)
    #pragma unroll
    for (int off = 1; off <= 2; off <<= 1){
      float om0 = __shfl_xor_sync(0xffffffff, m0, off);
      float os0 = __shfl_xor_sync(0xffffffff, s0, off);
      float om1 = __shfl_xor_sync(0xffffffff, m1, off);
      float os1 = __shfl_xor_sync(0xffffffff, s1, off);
      merge2(m0, s0, om0, os0);
      merge2(m1, s1, om1, os1);
    }
    if (tig == 0){
      sM[warp_n*128 + r0] = m0; sS[warp_n*128 + r0] = s0;
      sM[warp_n*128 + r1] = m1; sS[warp_n*128 + r1] = s1;
    }
  }
  __syncthreads();
  if (t < 128){
    float m = sM[t], ss = sS[t];
    merge2(m, ss, sM[128 + t], sS[128 + t]);
    g_pmax[t*NT_L + tile] = m;
    g_psum[t*NT_L + tile] = ss;
  }
}

// ---------------- fused: row reduce + in-place logp + argmax -----------------
// Per block = one batch row. Reduces 313 tile partials to (m, ls), then
// rewrites out[s,b,:] in place: logp = fl(fl(x - m) - ls), and argmaxes the
// ROUNDED values, first-index ties (matches jnp.argmax(log_softmax(x))).
__global__ __launch_bounds__(512) void k_write(float* __restrict__ out, int s)
{
  int b = blockIdx.x, t = threadIdx.x;
  __shared__ float sm[512]; __shared__ float ssm[512];
  float m = -3.402823466e38f; float ssum = 0.f;
  for (int tile = t; tile < NT_L; tile += 512)
    merge2(m, ssum, g_pmax[b*NT_L+tile], g_psum[b*NT_L+tile]);
  sm[t] = m; ssm[t] = ssum;
  __syncthreads();
  for (int off = 256; off; off >>= 1){
    if (t < off){
      float m2 = sm[t]; float s2 = ssm[t];
      merge2(m2, s2, sm[t+off], ssm[t+off]);
      sm[t] = m2; ssm[t] = s2;
    }
    __syncthreads();
  }
  m = sm[0];
  float ls = logf(ssm[0]);
  __syncthreads();

  float4* rowp = (float4*)(out + (long)s*BB*VV + (long)b*VV);
  float bm = -3.402823466e38f; int bi_ = 0x7fffffff;
  for (int p = t; p < VV/4; p += 512){
    float4 v = rowp[p];
    float r0 = __fsub_rn(__fsub_rn(v.x, m), ls);
    float r1 = __fsub_rn(__fsub_rn(v.y, m), ls);
    float r2 = __fsub_rn(__fsub_rn(v.z, m), ls);
    float r3 = __fsub_rn(__fsub_rn(v.w, m), ls);
    rowp[p] = make_float4(r0, r1, r2, r3);
    int n = p*4;   // ascending + strictly-greater => thread-local first idx
    if (r0 > bm){ bm = r0; bi_ = n;     }
    if (r1 > bm){ bm = r1; bi_ = n + 1; }
    if (r2 > bm){ bm = r2; bi_ = n + 2; }
    if (r3 > bm){ bm = r3; bi_ = n + 3; }
  }
  __shared__ float sv[512]; __shared__ int si[512];
  sv[t] = bm; si[t] = bi_;
  __syncthreads();
  for (int off = 256; off; off >>= 1){
    if (t < off){
      float ov = sv[t+off]; int oi = si[t+off];
      if (ov > sv[t] || (ov == sv[t] && oi < si[t])){ sv[t] = ov; si[t] = oi; }
    }
    __syncthreads();
  }
  if (t == 0) g_eid[b] = si[0];
}

// ---------------- pr1 = relu([emb[eid], h] @ W1^T + b1)  (R10) ---------------
__global__ __launch_bounds__(128) void k_pr1(
  const float* __restrict__ emb, const float* __restrict__ W1,
  const float* __restrict__ b1, int i)
{
  __shared__ float sW[4*768];
  const float* h = (i & 1) ? g_hA : g_hB;
  int j0 = blockIdx.x*4, tid = threadIdx.x;
  for (int p = tid; p < 4*192; p += 128){
    int r = p / 192, c4 = p - r*192;
    ((float4*)&sW[r*768])[c4] = ((const float4*)(W1 + (j0+r)*768))[c4];
  }
  __syncthreads();
  int b = tid;
  const float* xe = emb + (long)g_eid[b]*EE;   // g_eid already = next_eid
  const float* hb = h + b*HH;
  float acc[4] = {0,0,0,0};
  #pragma unroll 4
  for (int k = 0; k < EE; k += 4){
    float4 xv = *(const float4*)(xe + k);
    #pragma unroll
    for (int jj = 0; jj < 4; jj++)
      acc[jj] += dot4(xv, *(const float4*)&sW[jj*768 + k]);
  }
  #pragma unroll 4
  for (int k = 0; k < HH; k += 4){
    float4 hv = *(const float4*)(hb + k);
    #pragma unroll
    for (int jj = 0; jj < 4; jj++)
      acc[jj] += dot4(hv, *(const float4*)&sW[jj*768 + 256 + k]);
  }
  #pragma unroll
  for (int jj = 0; jj < 4; jj++)
    g_ph[b*HH + j0 + jj] = fmaxf(acc[jj] + b1[j0+jj], 0.f);
}

// ---------------- pr = sigmoid(relu(pr1) @ W2^T + b2)  (R10) -----------------
__global__ __launch_bounds__(128) void k_pr2(
  const float* __restrict__ W2, const float* __restrict__ b2,
  float* __restrict__ out, int s)
{
  int b = blockIdx.x, t = threadIdx.x;
  float acc = 0.f;
  for (int k = t; k < HH; k += 128) acc += g_ph[b*HH + k] * W2[k];
  __shared__ float red[128];
  red[t] = acc;
  __syncthreads();
  for (int off = 64; off; off >>= 1){
    if (t < off) red[t] = __fadd_rn(red[t], red[t+off]);
    __syncthreads();
  }
  if (t == 0){
    float pr = sigf(red[0] + b2[0]);
    out[(long)TTRG*BB*VV + (long)s*BB + b] = pr;
    g_rate[b] = pr;
  }
}

// ---------------- host driver ------------------------------------------------
extern "C" void kernel_launch(void* const* d_in, const int* in_sizes, int n_in,
                              void* d_out, int out_size)
{
  (void)in_sizes; (void)n_in; (void)out_size;
  const float* src      = (const float*)d_in[0];
  const int*   src_len  = (const int*)  d_in[1];
  const int*   trg_eid  = (const int*)  d_in[2];
  const float* trg_rate = (const float*)d_in[3];
  const float* emb      = (const float*)d_in[4];
  const float* enc_Wi   = (const float*)d_in[5];
  const float* enc_Wh   = (const float*)d_in[6];
  const float* enc_bi   = (const float*)d_in[7];
  const float* enc_bh   = (const float*)d_in[8];
  const float* dec_Wi   = (const float*)d_in[9];
  const float* dec_Wh   = (const float*)d_in[10];
  const float* dec_bi   = (const float*)d_in[11];
  const float* dec_bh   = (const float*)d_in[12];
  const float* We       = (const float*)d_in[13];
  const float* be       = (const float*)d_in[14];
  const float* W1       = (const float*)d_in[15];
  const float* b1       = (const float*)d_in[16];
  const float* W2       = (const float*)d_in[17];
  const float* b2       = (const float*)d_in[18];
  float* out = (float*)d_out;

  k_init<<<2560, 256>>>(trg_eid, trg_rate, out);

  // ---- encoder: 64 sequential GRU steps (h ping-pongs A<->B, ends in A)
  for (int t = 0; t < TSRC; t++)
    k_enc<<<128, 512>>>(src, src_len, enc_Wi, enc_Wh, enc_bi, enc_bh, t);

  // ---- decoder: 49 sequential steps, output index s = i+1
  for (int i = 0; i < TTRG - 1; i++){
    k_dec_gru<<<128, 512>>>(emb, dec_Wi, dec_Wh, dec_bi, dec_bh, i);
    k_logits<<<NT_L, 256>>>(We, be, out, i, i + 1);   // 4xTF32 tensor cores
    k_write<<<128, 512>>>(out, i + 1);                // reduce + logp + argmax
    k_pr1<<<128, 128>>>(emb, W1, b1, i);
    k_pr2<<<128, 128>>>(W2, b2, out, i + 1);
  }
}

// round 14
// speedup vs baseline: 1.1746x; 1.0567x over previous
#include <cuda_runtime.h>
#include <math.h>
#include <stdint.h>

#define BB   128
#define HH   512
#define INP  256
#define EE   256
#define VV   20000
#define TSRC 64
#define TTRG 50

// logits GEMM tiling (tensor core): BM=128, BN=48, 417 tiles, 2 CTAs/SM
#define BN_L 48
#define NT_L 417          // ceil(20000/48)
#define AST  36           // sA row stride (floats): conflict-free frag loads
#define BST  36           // sB row stride

// ---------------- persistent device scratch (no allocations) ----------------
__device__ float g_hA[BB*HH];
__device__ float g_hB[BB*HH];
__device__ float g_pmax[BB*NT_L];
__device__ float g_psum[BB*NT_L];
__device__ int   g_eid[BB];                // decoder carry: token id
__device__ float g_rate[BB];               // decoder carry: rate
__device__ float g_ph[BB*HH];              // relu(pr1)
__device__ float g_gix[(long)TSRC*1536*BB];// encoder x-part, [t][g*512+j][b]

__device__ __forceinline__ float sigf(float x){ return 1.f/(1.f+expf(-x)); }
__device__ __forceinline__ float dot4(float4 a, float4 b){
  return a.x*b.x + a.y*b.y + a.z*b.z + a.w*b.w;
}
// merge (max-value, sum-of-exp-relative-to-max). Safe with -FLT_MAX sentinel.
__device__ __forceinline__ void merge2(float& m, float& s, float om, float os){
  if (om > m){ s = s*__expf(m-om) + os; m = om; }
  else       { s = s + os*__expf(om-m); }
}
// split fp32 into two tf32 values (hi + lo); 3-product MMA ~ fp32-class
__device__ __forceinline__ void split_tf32(float x, uint32_t& hi, uint32_t& lo){
  uint32_t h_; asm("cvt.rna.tf32.f32 %0, %1;" : "=r"(h_) : "f"(x));
  float l = __fsub_rn(x, __uint_as_float(h_));
  asm("cvt.rna.tf32.f32 %0, %1;" : "=r"(lo) : "f"(l));
  hi = h_;
}
__device__ __forceinline__ void mma8(float* d,
  uint32_t a0,uint32_t a1,uint32_t a2,uint32_t a3, uint32_t b0,uint32_t b1){
  asm volatile("mma.sync.aligned.m16n8k8.row.col.f32.tf32.tf32.f32 "
    "{%0,%1,%2,%3}, {%4,%5,%6,%7}, {%8,%9}, {%0,%1,%2,%3};"
    : "+f"(d[0]),"+f"(d[1]),"+f"(d[2]),"+f"(d[3])
    : "r"(a0),"r"(a1),"r"(a2),"r"(a3),"r"(b0),"r"(b1));
}

// ---------------- init: zero step-0 outputs, h0, seed decoder carry ----------
__global__ void k_init(const int* __restrict__ trg_eid,
                       const float* __restrict__ trg_rate,
                       float* __restrict__ out)
{
  long idx = (long)blockIdx.x*blockDim.x + threadIdx.x;
  const long NZ = (long)BB*VV/4;               // 640000 float4
  float4 z = make_float4(0.f,0.f,0.f,0.f);
  if (idx < NZ) ((float4*)out)[idx] = z;       // eid_result[0] = 0
  if (idx < BB*HH/4) ((float4*)g_hA)[idx] = z; // h0 = 0
  if (idx < BB) {
    out[(long)TTRG*BB*VV + idx] = 0.f;         // rate_result[0] = 0
    g_eid[idx]  = trg_eid[idx];                // trg_eid[0, b]
    g_rate[idx] = trg_rate[idx];               // trg_rate[0, b]
  }
}

// ---------------- encoder x-part precompute: gi_x = src @ Wi^T ---------------
// One-off, fully parallel: grid = TSRC*128 (t, j-block of 4), block 128 (b).
// Output transposed: g_gix[(t*1536 + g*512 + j)*BB + b] for coalesced access.
__global__ __launch_bounds__(128) void k_gix(
  const float* __restrict__ src, const float* __restrict__ Wi)
{
  __shared__ float sWi[12*INP];              // 12KB
  int t  = blockIdx.x >> 7;
  int jb = blockIdx.x & 127;
  int j0 = jb*4;
  int tid = threadIdx.x;
  for (int p = tid; p < 12*(INP/4); p += 128){
    int r = p >> 6, c4 = p & 63;
    int g = r >> 2, jj = r & 3;
    ((float4*)sWi)[p] = ((const float4*)(Wi + (g*HH + j0 + jj)*INP))[c4];
  }
  __syncthreads();
  int b = tid;
  const float* x = src + ((long)t*BB + b)*INP;
  float acc[12];
  #pragma unroll
  for (int q = 0; q < 12; q++) acc[q] = 0.f;
  #pragma unroll 4
  for (int k = 0; k < INP; k += 4){
    float4 xv = *(const float4*)(x + k);
    #pragma unroll
    for (int q = 0; q < 12; q++)
      acc[q] += dot4(xv, *(const float4*)&sWi[q*INP + k]);
  }
  #pragma unroll
  for (int g = 0; g < 3; g++)
    #pragma unroll
    for (int jj = 0; jj < 4; jj++)
      g_gix[((long)t*1536 + g*512 + j0 + jj)*BB + b] = acc[g*4 + jj];
}

// ---------------- encoder GRU step (h-part only; k-split x4, 512 thr) --------
// grid 128 (4 hidden units each), block 512: tid = b + 128*kq.
__global__ __launch_bounds__(512) void k_enc(
  const int* __restrict__ src_len,
  const float* __restrict__ Wh,
  const float* __restrict__ bi, const float* __restrict__ bh, int t)
{
  __shared__ float sbuf[16*512];            // 32KB: sWh 12x512, overlay sP 16x512
  float* sWh = sbuf;
  const float* hin  = (t & 1) ? g_hB : g_hA;
  float*       hout = (t & 1) ? g_hA : g_hB;
  int j0 = blockIdx.x * 4;
  int tid = threadIdx.x;
  int b = tid & 127, kq = tid >> 7;
  for (int p = tid; p < 12*(HH/4); p += 512){
    int r = p >> 7, c4 = p & 127;
    int g = r >> 2, jj = r & 3;
    ((float4*)sWh)[p] = ((const float4*)(Wh + (g*HH + j0 + jj)*HH))[c4];
  }
  __syncthreads();
  const float* h = hin + b*HH;
  float aR[4]={0,0,0,0}, aZ[4]={0,0,0,0}, aNH[4]={0,0,0,0};
  {
    int k0 = kq*128;
    #pragma unroll 4
    for (int k = k0; k < k0+128; k += 4){
      float4 hv = *(const float4*)(h + k);
      #pragma unroll
      for (int jj = 0; jj < 4; jj++){
        aR[jj]  += dot4(hv, *(const float4*)&sWh[(    jj)*HH + k]);
        aZ[jj]  += dot4(hv, *(const float4*)&sWh[(4 + jj)*HH + k]);
        aNH[jj] += dot4(hv, *(const float4*)&sWh[(8 + jj)*HH + k]);
      }
    }
  }
  __syncthreads();                          // weight reads done
  float* sP = sbuf;                         // overlay: 12 x 512 partials
  #pragma unroll
  for (int jj = 0; jj < 4; jj++){
    sP[(0 + jj)*512 + tid] = aR[jj];
    sP[(4 + jj)*512 + tid] = aZ[jj];
    sP[(8 + jj)*512 + tid] = aNH[jj];
  }
  __syncthreads();
  if (tid < 128){
    int bb = tid;
    bool act = t < src_len[bb];
    const float* hb = hin + bb*HH;
    const float* gix = g_gix + (long)t*1536*BB;
    #pragma unroll
    for (int jj = 0; jj < 4; jj++){
      int j = j0 + jj;
      float vR  = ((sP[(0+jj)*512+bb] + sP[(0+jj)*512+bb+128])
                 + (sP[(0+jj)*512+bb+256] + sP[(0+jj)*512+bb+384]))
                 + gix[(0*512 + j)*BB + bb];
      float vZ  = ((sP[(4+jj)*512+bb] + sP[(4+jj)*512+bb+128])
                 + (sP[(4+jj)*512+bb+256] + sP[(4+jj)*512+bb+384]))
                 + gix[(1*512 + j)*BB + bb];
      float vNH = ((sP[(8+jj)*512+bb] + sP[(8+jj)*512+bb+128])
                 + (sP[(8+jj)*512+bb+256] + sP[(8+jj)*512+bb+384]));
      float vNX = gix[(2*512 + j)*BB + bb];
      float r = sigf(vR + bi[j]      + bh[j]);
      float z = sigf(vZ + bi[HH+j]   + bh[HH+j]);
      float n = tanhf(vNX + bi[2*HH+j] + r*(vNH + bh[2*HH+j]));
      float hv = (1.f - z)*n + z*hb[j];
      hout[bb*HH + j] = act ? hv : hb[j];
    }
  }
}

// ---------------- decoder GRU step (k-split x4, 512 threads, R10) ------------
__global__ __launch_bounds__(512) void k_dec_gru(
  const float* __restrict__ emb,
  const float* __restrict__ Wi, const float* __restrict__ Wh,
  const float* __restrict__ bi, const float* __restrict__ bh, int i)
{
  __shared__ float sbuf[12*260 + 12*HH];   // 37KB; overlay sP[16*512]
  float* sWi = sbuf;                        // 12 rows x 260 (257 padded)
  float* sWh = sbuf + 12*260;
  const float* hin  = (i & 1) ? g_hB : g_hA;
  float*       hout = (i & 1) ? g_hA : g_hB;
  int j0 = blockIdx.x * 4;
  int tid = threadIdx.x;
  int b = tid & 127, kq = tid >> 7;
  for (int p = tid; p < 12*257; p += 512){
    int r = p / 257, c = p - r*257;
    int g = r >> 2, jj = r & 3;
    sWi[r*260 + c] = Wi[(g*HH + j0 + jj)*257 + c];
  }
  for (int p = tid; p < 12*(HH/4); p += 512){
    int r = p >> 7, c4 = p & 127;
    int g = r >> 2, jj = r & 3;
    ((float4*)sWh)[p] = ((const float4*)(Wh + (g*HH + j0 + jj)*HH))[c4];
  }
  __syncthreads();
  const float* xe = emb + (long)g_eid[b]*EE;
  const float* h = hin + b*HH;
  float aR[4]={0,0,0,0}, aZ[4]={0,0,0,0}, aNX[4]={0,0,0,0}, aNH[4]={0,0,0,0};
  {
    int k0 = kq*64;
    #pragma unroll 4
    for (int k = k0; k < k0+64; k += 4){
      float4 xv = *(const float4*)(xe + k);
      #pragma unroll
      for (int jj = 0; jj < 4; jj++){
        aR[jj]  += dot4(xv, *(const float4*)&sWi[(    jj)*260 + k]);
        aZ[jj]  += dot4(xv, *(const float4*)&sWi[(4 + jj)*260 + k]);
        aNX[jj] += dot4(xv, *(const float4*)&sWi[(8 + jj)*260 + k]);
      }
    }
  }
  if (kq == 0){                             // rate column (k = 256)
    float rate = g_rate[b];
    #pragma unroll
    for (int jj = 0; jj < 4; jj++){
      aR[jj]  += rate * sWi[(    jj)*260 + 256];
      aZ[jj]  += rate * sWi[(4 + jj)*260 + 256];
      aNX[jj] += rate * sWi[(8 + jj)*260 + 256];
    }
  }
  {
    int k0 = kq*128;
    #pragma unroll 4
    for (int k = k0; k < k0+128; k += 4){
      float4 hv = *(const float4*)(h + k);
      #pragma unroll
      for (int jj = 0; jj < 4; jj++){
        aR[jj]  += dot4(hv, *(const float4*)&sWh[(    jj)*HH + k]);
        aZ[jj]  += dot4(hv, *(const float4*)&sWh[(4 + jj)*HH + k]);
        aNH[jj] += dot4(hv, *(const float4*)&sWh[(8 + jj)*HH + k]);
      }
    }
  }
  __syncthreads();
  float* sP = sbuf;
  #pragma unroll
  for (int jj = 0; jj < 4; jj++){
    sP[( 0 + jj)*512 + tid] = aR[jj];
    sP[( 4 + jj)*512 + tid] = aZ[jj];
    sP[( 8 + jj)*512 + tid] = aNX[jj];
    sP[(12 + jj)*512 + tid] = aNH[jj];
  }
  __syncthreads();
  if (tid < 128){
    int bb = tid;
    const float* hb = hin + bb*HH;
    #pragma unroll
    for (int jj = 0; jj < 4; jj++){
      float vR  = ((sP[( 0+jj)*512+bb] + sP[( 0+jj)*512+bb+128])
                 + (sP[( 0+jj)*512+bb+256] + sP[( 0+jj)*512+bb+384]));
      float vZ  = ((sP[( 4+jj)*512+bb] + sP[( 4+jj)*512+bb+128])
                 + (sP[( 4+jj)*512+bb+256] + sP[( 4+jj)*512+bb+384]));
      float vNX = ((sP[( 8+jj)*512+bb] + sP[( 8+jj)*512+bb+128])
                 + (sP[( 8+jj)*512+bb+256] + sP[( 8+jj)*512+bb+384]));
      float vNH = ((sP[(12+jj)*512+bb] + sP[(12+jj)*512+bb+128])
                 + (sP[(12+jj)*512+bb+256] + sP[(12+jj)*512+bb+384]));
      int j = j0 + jj;
      float r = sigf(vR + bi[j]      + bh[j]);
      float z = sigf(vZ + bi[HH+j]   + bh[HH+j]);
      float n = tanhf(vNX + bi[2*HH+j] + r*(vNH + bh[2*HH+j]));
      hout[bb*HH + j] = (1.f - z)*n + z*hb[j];
    }
  }
}

// ---------------- logits GEMM via 3xTF32 tensor cores, BN=48 -----------------
// C[128,48/tile] = h @ We^T + be. 256 threads = 8 warps (4M x 2N), warp tile
// 32x24 (2 m16 x 3 n8). 3 products (AhBh + AhBl + AlBh); lo*lo dropped
// (error ~1e-7, fp32-class). Raw logits -> out[s]; tile stats -> g_pmax/psum.
__global__ __launch_bounds__(256, 2) void k_logits(
  const float* __restrict__ We, const float* __restrict__ be,
  float* __restrict__ out, int i, int s)
{
  __shared__ float sA[128*AST];             // 18.4KB  h tile [m][k]
  __shared__ float sB[BN_L*BST];            // 6.9KB   We tile [n][k]
  __shared__ float sM[2*128], sS[2*128];
  const float* h = (i & 1) ? g_hA : g_hB;
  int tile = blockIdx.x;
  int n0 = tile * BN_L;
  int t = threadIdx.x;
  int lane = t & 31, wid = t >> 5;
  int gid = lane >> 2, tig = lane & 3;
  int warp_m = wid >> 1, warp_n = wid & 1;

  float acc[2][3][4];
  #pragma unroll
  for (int mt = 0; mt < 2; mt++)
    #pragma unroll
    for (int nt = 0; nt < 3; nt++)
      #pragma unroll
      for (int q = 0; q < 4; q++) acc[mt][nt][q] = 0.f;

  for (int k0 = 0; k0 < HH; k0 += 32){
    #pragma unroll
    for (int ld = 0; ld < 4; ld++){         // A: 128 rows x 32 k (1024 float4)
      int p = t + ld*256;
      int row = p >> 3, c4 = p & 7;
      float4 v = *(const float4*)(h + row*HH + k0 + c4*4);
      *(float4*)&sA[row*AST + c4*4] = v;
    }
    for (int p = t; p < BN_L*8; p += 256){  // B: 48 n-rows x 32 k (384 float4)
      int n = p >> 3, c4 = p & 7;
      int nn = n0 + n; if (nn >= VV) nn = 0;   // clamp; discarded in epilogue
      float4 v = *(const float4*)(We + (long)nn*HH + k0 + c4*4);
      *(float4*)&sB[n*BST + c4*4] = v;
    }
    __syncthreads();
    #pragma unroll
    for (int kk = 0; kk < 32; kk += 8){
      uint32_t Ah[2][4], Al[2][4];
      #pragma unroll
      for (int mt = 0; mt < 2; mt++){
        int rb = warp_m*32 + mt*16 + gid;
        split_tf32(sA[(rb    )*AST + kk + tig    ], Ah[mt][0], Al[mt][0]);
        split_tf32(sA[(rb + 8)*AST + kk + tig    ], Ah[mt][1], Al[mt][1]);
        split_tf32(sA[(rb    )*AST + kk + tig + 4], Ah[mt][2], Al[mt][2]);
        split_tf32(sA[(rb + 8)*AST + kk + tig + 4], Ah[mt][3], Al[mt][3]);
      }
      uint32_t Bh[3][2], Bl[3][2];
      #pragma unroll
      for (int nt = 0; nt < 3; nt++){
        int nb = warp_n*24 + nt*8 + gid;
        split_tf32(sB[nb*BST + kk + tig    ], Bh[nt][0], Bl[nt][0]);
        split_tf32(sB[nb*BST + kk + tig + 4], Bh[nt][1], Bl[nt][1]);
      }
      #pragma unroll
      for (int mt = 0; mt < 2; mt++)
        #pragma unroll
        for (int nt = 0; nt < 3; nt++){
          float* d = acc[mt][nt];
          mma8(d, Ah[mt][0],Ah[mt][1],Ah[mt][2],Ah[mt][3], Bl[nt][0],Bl[nt][1]);
          mma8(d, Al[mt][0],Al[mt][1],Al[mt][2],Al[mt][3], Bh[nt][0],Bh[nt][1]);
          mma8(d, Ah[mt][0],Ah[mt][1],Ah[mt][2],Ah[mt][3], Bh[nt][0],Bh[nt][1]);
        }
    }
    __syncthreads();
  }

  // ---- epilogue: bias, store raw logits, per-row stats ----
  float* orow = out + (long)s*BB*VV;
  #pragma unroll
  for (int mt = 0; mt < 2; mt++){
    int r0 = warp_m*32 + mt*16 + gid;
    int r1 = r0 + 8;
    float m0 = -3.402823466e38f, s0 = 0.f;
    float m1 = -3.402823466e38f, s1 = 0.f;
    #pragma unroll
    for (int nt = 0; nt < 3; nt++){
      int c0 = n0 + warp_n*24 + nt*8 + tig*2;
      bool ok0 = (c0     < VV);
      bool ok1 = (c0 + 1 < VV);
      float b0v = ok0 ? be[c0]   : 0.f;
      float b1v = ok1 ? be[c0+1] : 0.f;
      float x00 = acc[mt][nt][0] + b0v;   // (r0, c0)
      float x01 = acc[mt][nt][1] + b1v;   // (r0, c0+1)
      float x10 = acc[mt][nt][2] + b0v;   // (r1, c0)
      float x11 = acc[mt][nt][3] + b1v;   // (r1, c0+1)
      if (ok0 && ok1){
        *(float2*)&orow[(long)r0*VV + c0] = make_float2(x00, x01);
        *(float2*)&orow[(long)r1*VV + c0] = make_float2(x10, x11);
      } else {
        if (ok0){ orow[(long)r0*VV + c0] = x00; orow[(long)r1*VV + c0] = x10; }
        if (ok1){ orow[(long)r0*VV + c0+1] = x01; orow[(long)r1*VV + c0+1] = x11; }
      }
      if (ok0){ merge2(m0, s0, x00, 1.f); merge2(m1, s1, x10, 1.f); }
      if (ok1){ merge2(m0, s0, x01, 1.f); merge2(m1, s1, x11, 1.f); }
    }
    #pragma unroll
    for (int off = 1; off <= 2; off <<= 1){
      float om0 = __shfl_xor_sync(0xffffffff, m0, off);
      float os0 = __shfl_xor_sync(0xffffffff, s0, off);
      float om1 = __shfl_xor_sync(0xffffffff, m1, off);
      float os1 = __shfl_xor_sync(0xffffffff, s1, off);
      merge2(m0, s0, om0, os0);
      merge2(m1, s1, om1, os1);
    }
    if (tig == 0){
      sM[warp_n*128 + r0] = m0; sS[warp_n*128 + r0] = s0;
      sM[warp_n*128 + r1] = m1; sS[warp_n*128 + r1] = s1;
    }
  }
  __syncthreads();
  if (t < 128){
    float m = sM[t], ss = sS[t];
    merge2(m, ss, sM[128 + t], sS[128 + t]);
    g_pmax[t*NT_L + tile] = m;
    g_psum[t*NT_L + tile] = ss;
  }
}

// ---------------- fused: row reduce + in-place logp + argmax -----------------
// Per block = one batch row. Reduces 417 tile partials to (m, ls), then
// rewrites out[s,b,:] in place: logp = fl(fl(x - m) - ls), and argmaxes the
// ROUNDED values, first-index ties (matches jnp.argmax(log_softmax(x))).
__global__ __launch_bounds__(512) void k_write(float* __restrict__ out, int s)
{
  int b = blockIdx.x, t = threadIdx.x;
  __shared__ float sm[512]; __shared__ float ssm[512];
  float m = -3.402823466e38f; float ssum = 0.f;
  for (int tile = t; tile < NT_L; tile += 512)
    merge2(m, ssum, g_pmax[b*NT_L+tile], g_psum[b*NT_L+tile]);
  sm[t] = m; ssm[t] = ssum;
  __syncthreads();
  for (int off = 256; off; off >>= 1){
    if (t < off){
      float m2 = sm[t]; float s2 = ssm[t];
      merge2(m2, s2, sm[t+off], ssm[t+off]);
      sm[t] = m2; ssm[t] = s2;
    }
    __syncthreads();
  }
  m = sm[0];
  float ls = logf(ssm[0]);
  __syncthreads();

  float4* rowp = (float4*)(out + (long)s*BB*VV + (long)b*VV);
  float bm = -3.402823466e38f; int bi_ = 0x7fffffff;
  for (int p = t; p < VV/4; p += 512){
    float4 v = rowp[p];
    float r0 = __fsub_rn(__fsub_rn(v.x, m), ls);
    float r1 = __fsub_rn(__fsub_rn(v.y, m), ls);
    float r2 = __fsub_rn(__fsub_rn(v.z, m), ls);
    float r3 = __fsub_rn(__fsub_rn(v.w, m), ls);
    rowp[p] = make_float4(r0, r1, r2, r3);
    int n = p*4;   // ascending + strictly-greater => thread-local first idx
    if (r0 > bm){ bm = r0; bi_ = n;     }
    if (r1 > bm){ bm = r1; bi_ = n + 1; }
    if (r2 > bm){ bm = r2; bi_ = n + 2; }
    if (r3 > bm){ bm = r3; bi_ = n + 3; }
  }
  __shared__ float sv[512]; __shared__ int si[512];
  sv[t] = bm; si[t] = bi_;
  __syncthreads();
  for (int off = 256; off; off >>= 1){
    if (t < off){
      float ov = sv[t+off]; int oi = si[t+off];
      if (ov > sv[t] || (ov == sv[t] && oi < si[t])){ sv[t] = ov; si[t] = oi; }
    }
    __syncthreads();
  }
  if (t == 0) g_eid[b] = si[0];
}

// ---------------- pr1 = relu([emb[eid], h] @ W1^T + b1) ----------------------
__global__ __launch_bounds__(128) void k_pr1(
  const float* __restrict__ emb, const float* __restrict__ W1,
  const float* __restrict__ b1, int i)
{
  __shared__ float sW[4*768];
  const float* h = (i & 1) ? g_hA : g_hB;
  int j0 = blockIdx.x*4, tid = threadIdx.x;
  for (int p = tid; p < 4*192; p += 128){
    int r = p / 192, c4 = p - r*192;
    ((float4*)&sW[r*768])[c4] = ((const float4*)(W1 + (j0+r)*768))[c4];
  }
  __syncthreads();
  int b = tid;
  const float* xe = emb + (long)g_eid[b]*EE;   // g_eid already = next_eid
  const float* hb = h + b*HH;
  float acc[4] = {0,0,0,0};
  #pragma unroll 4
  for (int k = 0; k < EE; k += 4){
    float4 xv = *(const float4*)(xe + k);
    #pragma unroll
    for (int jj = 0; jj < 4; jj++)
      acc[jj] += dot4(xv, *(const float4*)&sW[jj*768 + k]);
  }
  #pragma unroll 4
  for (int k = 0; k < HH; k += 4){
    float4 hv = *(const float4*)(hb + k);
    #pragma unroll
    for (int jj = 0; jj < 4; jj++)
      acc[jj] += dot4(hv, *(const float4*)&sW[jj*768 + 256 + k]);
  }
  #pragma unroll
  for (int jj = 0; jj < 4; jj++)
    g_ph[b*HH + j0 + jj] = fmaxf(acc[jj] + b1[j0+jj], 0.f);
}

// ---------------- pr = sigmoid(relu(pr1) @ W2^T + b2) ------------------------
__global__ __launch_bounds__(128) void k_pr2(
  const float* __restrict__ W2, const float* __restrict__ b2,
  float* __restrict__ out, int s)
{
  int b = blockIdx.x, t = threadIdx.x;
  float acc = 0.f;
  for (int k = t; k < HH; k += 128) acc += g_ph[b*HH + k] * W2[k];
  __shared__ float red[128];
  red[t] = acc;
  __syncthreads();
  for (int off = 64; off; off >>= 1){
    if (t < off) red[t] = __fadd_rn(red[t], red[t+off]);
    __syncthreads();
  }
  if (t == 0){
    float pr = sigf(red[0] + b2[0]);
    out[(long)TTRG*BB*VV + (long)s*BB + b] = pr;
    g_rate[b] = pr;
  }
}

// ---------------- host driver ------------------------------------------------
extern "C" void kernel_launch(void* const* d_in, const int* in_sizes, int n_in,
                              void* d_out, int out_size)
{
  (void)in_sizes; (void)n_in; (void)out_size;
  const float* src      = (const float*)d_in[0];
  const int*   src_len  = (const int*)  d_in[1];
  const int*   trg_eid  = (const int*)  d_in[2];
  const float* trg_rate = (const float*)d_in[3];
  const float* emb      = (const float*)d_in[4];
  const float* enc_Wi   = (const float*)d_in[5];
  const float* enc_Wh   = (const float*)d_in[6];
  const float* enc_bi   = (const float*)d_in[7];
  const float* enc_bh   = (const float*)d_in[8];
  const float* dec_Wi   = (const float*)d_in[9];
  const float* dec_Wh   = (const float*)d_in[10];
  const float* dec_bi   = (const float*)d_in[11];
  const float* dec_bh   = (const float*)d_in[12];
  const float* We       = (const float*)d_in[13];
  const float* be       = (const float*)d_in[14];
  const float* W1       = (const float*)d_in[15];
  const float* b1       = (const float*)d_in[16];
  const float* W2       = (const float*)d_in[17];
  const float* b2       = (const float*)d_in[18];
  float* out = (float*)d_out;

  k_init<<<2560, 256>>>(trg_eid, trg_rate, out);

  // ---- encoder x-part: one big parallel GEMM (no h dependence)
  k_gix<<<TSRC*128, 128>>>(src, enc_Wi);

  // ---- encoder: 64 sequential GRU steps (h ping-pongs A<->B, ends in A)
  for (int t = 0; t < TSRC; t++)
    k_enc<<<128, 512>>>(src_len, enc_Wh, enc_bi, enc_bh, t);

  // ---- decoder: 49 sequential steps, output index s = i+1
  for (int i = 0; i < TTRG - 1; i++){
    k_dec_gru<<<128, 512>>>(emb, dec_Wi, dec_Wh, dec_bi, dec_bh, i);
    k_logits<<<NT_L, 256>>>(We, be, out, i, i + 1);   // 3xTF32 tensor cores
    k_write<<<128, 512>>>(out, i + 1);                // reduce + logp + argmax
    k_pr1<<<128, 128>>>(emb, W1, b1, i);
    k_pr2<<<128, 128>>>(W2, b2, out, i + 1);
  }
}